// round 1
// baseline (speedup 1.0000x reference)
#include <cuda_runtime.h>
#include <cuda_bf16.h>
#include <cstddef>

// Problem constants
#define B_SZ   2
#define NSEQ   2048
#define DMODEL 1024
#define NHEAD  16
#define HDIM   64
#define MTOT   (B_SZ * NSEQ)      // 4096
#define KTOT   DMODEL             // 1024
#define NTOT   DMODEL             // 1024
#define BH     (B_SZ * NHEAD)     // 32

// Scratch (static device arrays; no allocation allowed)
__device__ float g_Q[BH * NSEQ * HDIM];   // [bh, n, hd]
__device__ float g_K[BH * NSEQ * HDIM];
__device__ float g_V[BH * NSEQ * HDIM];
__device__ float g_A[MTOT * DMODEL];      // attention output in [B,N,D]

// ---------------------------------------------------------------------------
// Tiled fp32 GEMM:  C[m,n] = sum_k A[m,k] * W[n,k] + bias[n]
// A: [MTOT, KTOT] row-major.  W: [NTOT, KTOT] row-major (i.e. x @ W^T).
// MODE 0: C row-major [MTOT, NTOT]
// MODE 1: C scattered to head-split [bh, nseq, hd]  (for Q/K/V scratch)
// ---------------------------------------------------------------------------
#define BM 128
#define BN 128
#define BK 16

template <int MODE>
__global__ void __launch_bounds__(256, 2)
gemm_nt(const float* __restrict__ A, const float* __restrict__ W,
        const float* __restrict__ bias, float* __restrict__ C)
{
    __shared__ float As[BK][BM];
    __shared__ float Bs[BK][BN];

    const int tid = threadIdx.x;
    const int tx  = tid & 15;
    const int ty  = tid >> 4;
    const int m0  = blockIdx.y * BM;
    const int n0  = blockIdx.x * BN;

    float acc[8][8];
#pragma unroll
    for (int i = 0; i < 8; i++)
#pragma unroll
        for (int j = 0; j < 8; j++) acc[i][j] = 0.f;

    for (int k0 = 0; k0 < KTOT; k0 += BK) {
        // Cooperative load of A tile (128x16) and W tile (128x16), both NT.
#pragma unroll
        for (int it = 0; it < 2; it++) {
            int idx = tid * 2 + it;          // 0..511 float4 slots
            int r   = idx >> 2;              // 0..127 tile row
            int kq  = (idx & 3) * 4;         // k sub-offset 0/4/8/12
            float4 va = *(const float4*)(A + (size_t)(m0 + r) * KTOT + k0 + kq);
            As[kq + 0][r] = va.x; As[kq + 1][r] = va.y;
            As[kq + 2][r] = va.z; As[kq + 3][r] = va.w;
            float4 vb = *(const float4*)(W + (size_t)(n0 + r) * KTOT + k0 + kq);
            Bs[kq + 0][r] = vb.x; Bs[kq + 1][r] = vb.y;
            Bs[kq + 2][r] = vb.z; Bs[kq + 3][r] = vb.w;
        }
        __syncthreads();

#pragma unroll
        for (int k = 0; k < BK; k++) {
            float a[8], b[8];
#pragma unroll
            for (int i = 0; i < 8; i++) a[i] = As[k][ty * 8 + i];
#pragma unroll
            for (int j = 0; j < 8; j++) b[j] = Bs[k][tx * 8 + j];
#pragma unroll
            for (int i = 0; i < 8; i++)
#pragma unroll
                for (int j = 0; j < 8; j++) acc[i][j] += a[i] * b[j];
        }
        __syncthreads();
    }

    // Epilogue: bias + store
#pragma unroll
    for (int i = 0; i < 8; i++) {
        int m = m0 + ty * 8 + i;
#pragma unroll
        for (int j = 0; j < 8; j++) {
            int n = n0 + tx * 8 + j;
            float v = acc[i][j] + bias[n];
            if (MODE == 0) {
                C[(size_t)m * NTOT + n] = v;
            } else {
                int b  = m >> 11;          // m / 2048
                int ns = m & 2047;
                int h  = n >> 6;           // n / 64
                int hd = n & 63;
                C[(((size_t)(b * NHEAD + h) * NSEQ) + ns) * HDIM + hd] = v;
            }
        }
    }
}

// ---------------------------------------------------------------------------
// Fused flash attention (fp32).  Q,K,V: [BH, NSEQ, 64].
// Block: 64 q-rows x full head, loop over 32-row K/V tiles with online softmax.
// Output written directly in [B, N, D] layout for the O projection.
// ---------------------------------------------------------------------------
#define BR 64
#define BC 32

__global__ void __launch_bounds__(256, 4)
flash_attn(const float* __restrict__ Q, const float* __restrict__ K,
           const float* __restrict__ V, float* __restrict__ Out)
{
    __shared__ float QsT[64][65];   // [hd][qrow], pre-scaled
    __shared__ float KsT[64][33];   // [hd][kvrow]
    __shared__ float Vs[32][64];    // [kvrow][hd]
    __shared__ float PsT[32][65];   // [kvrow][qrow]

    const int tid = threadIdx.x;
    const int tx  = tid & 15;       // 16 cols of threads
    const int ty  = tid >> 4;       // 16 rows of threads
    const int bh  = blockIdx.y;
    const int q0  = blockIdx.x * BR;

    const float* Qb = Q + (size_t)bh * NSEQ * HDIM;
    const float* Kb = K + (size_t)bh * NSEQ * HDIM;
    const float* Vb = V + (size_t)bh * NSEQ * HDIM;

    // Load Q tile (64x64) transposed into QsT, pre-scaled by 1/sqrt(64)
#pragma unroll
    for (int it = 0; it < 4; it++) {
        int idx = tid * 4 + it;          // 0..1023 float4 slots
        int r   = idx >> 4;              // 0..63 q row
        int c4  = (idx & 15) * 4;        // hd offset
        float4 v = *(const float4*)(Qb + (size_t)(q0 + r) * HDIM + c4);
        QsT[c4 + 0][r] = v.x * 0.125f;
        QsT[c4 + 1][r] = v.y * 0.125f;
        QsT[c4 + 2][r] = v.z * 0.125f;
        QsT[c4 + 3][r] = v.w * 0.125f;
    }

    float o[4][4];
    float mI[4], lI[4];
#pragma unroll
    for (int i = 0; i < 4; i++) {
        mI[i] = -1e30f; lI[i] = 0.f;
#pragma unroll
        for (int j = 0; j < 4; j++) o[i][j] = 0.f;
    }
    const int r0 = ty * 4;

    for (int kt = 0; kt < NSEQ / BC; kt++) {
        __syncthreads();   // prev PV done; safe to overwrite Ks/Vs/PsT (also covers Q load on kt==0)

        // Load K tile transposed + V tile (each 32x64)
#pragma unroll
        for (int it = 0; it < 2; it++) {
            int idx = tid * 2 + it;      // 0..511 float4 slots
            int r   = idx >> 4;          // 0..31 kv row
            int c4  = (idx & 15) * 4;    // hd offset
            float4 vk = *(const float4*)(Kb + (size_t)(kt * BC + r) * HDIM + c4);
            KsT[c4 + 0][r] = vk.x; KsT[c4 + 1][r] = vk.y;
            KsT[c4 + 2][r] = vk.z; KsT[c4 + 3][r] = vk.w;
            float4 vv = *(const float4*)(Vb + (size_t)(kt * BC + r) * HDIM + c4);
            *(float4*)(&Vs[r][c4]) = vv;
        }
        __syncthreads();

        // S = Q K^T  (64x32), thread owns 4 rows x 2 cols
        float s0[4], s1[4];
#pragma unroll
        for (int i = 0; i < 4; i++) { s0[i] = 0.f; s1[i] = 0.f; }
        const int c0s = tx * 2;
#pragma unroll
        for (int k = 0; k < 64; k++) {
            float a0 = QsT[k][r0 + 0], a1 = QsT[k][r0 + 1];
            float a2 = QsT[k][r0 + 2], a3 = QsT[k][r0 + 3];
            float b0 = KsT[k][c0s + 0], b1 = KsT[k][c0s + 1];
            s0[0] += a0 * b0; s1[0] += a0 * b1;
            s0[1] += a1 * b0; s1[1] += a1 * b1;
            s0[2] += a2 * b0; s1[2] += a2 * b1;
            s0[3] += a3 * b0; s1[3] += a3 * b1;
        }

        // Online softmax per q-row (row stats shared by 16 threads via shfl;
        // lane = (ty&1)*16 + tx, so xor over bits 0..3 reduces across tx only)
#pragma unroll
        for (int i = 0; i < 4; i++) {
            float mx = fmaxf(s0[i], s1[i]);
#pragma unroll
            for (int off = 1; off < 16; off <<= 1)
                mx = fmaxf(mx, __shfl_xor_sync(0xffffffffu, mx, off));
            float mnew = fmaxf(mI[i], mx);
            float p0 = __expf(s0[i] - mnew);
            float p1 = __expf(s1[i] - mnew);
            float sum = p0 + p1;
#pragma unroll
            for (int off = 1; off < 16; off <<= 1)
                sum += __shfl_xor_sync(0xffffffffu, sum, off);
            float alpha = __expf(mI[i] - mnew);
            lI[i] = lI[i] * alpha + sum;
            mI[i] = mnew;
#pragma unroll
            for (int j = 0; j < 4; j++) o[i][j] *= alpha;
            PsT[c0s + 0][r0 + i] = p0;
            PsT[c0s + 1][r0 + i] = p1;
        }
        __syncthreads();

        // O += P V  (64x64), thread owns 4 rows x 4 hd cols
        const int c0v = tx * 4;
#pragma unroll
        for (int kc = 0; kc < 32; kc++) {
            float a0 = PsT[kc][r0 + 0], a1 = PsT[kc][r0 + 1];
            float a2 = PsT[kc][r0 + 2], a3 = PsT[kc][r0 + 3];
            float b0 = Vs[kc][c0v + 0], b1 = Vs[kc][c0v + 1];
            float b2 = Vs[kc][c0v + 2], b3 = Vs[kc][c0v + 3];
            o[0][0] += a0 * b0; o[0][1] += a0 * b1; o[0][2] += a0 * b2; o[0][3] += a0 * b3;
            o[1][0] += a1 * b0; o[1][1] += a1 * b1; o[1][2] += a1 * b2; o[1][3] += a1 * b3;
            o[2][0] += a2 * b0; o[2][1] += a2 * b1; o[2][2] += a2 * b2; o[2][3] += a2 * b3;
            o[3][0] += a3 * b0; o[3][1] += a3 * b1; o[3][2] += a3 * b2; o[3][3] += a3 * b3;
        }
    }

    // Normalize and store to [B, N, D] layout (row m = b*NSEQ+q, col = h*64+hd)
    const int bb = bh >> 4;
    const int h  = bh & 15;
#pragma unroll
    for (int i = 0; i < 4; i++) {
        float inv = 1.f / lI[i];
        int q = q0 + r0 + i;
#pragma unroll
        for (int j = 0; j < 4; j++) {
            int hd = tx * 4 + j;
            Out[((size_t)(bb * NSEQ + q)) * DMODEL + h * HDIM + hd] = o[i][j] * inv;
        }
    }
}

// ---------------------------------------------------------------------------
// Launch
// ---------------------------------------------------------------------------
extern "C" void kernel_launch(void* const* d_in, const int* in_sizes, int n_in,
                              void* d_out, int out_size)
{
    const float* x  = (const float*)d_in[0];
    const float* Wq = (const float*)d_in[1];
    const float* bq = (const float*)d_in[2];
    const float* Wk = (const float*)d_in[3];
    const float* bk = (const float*)d_in[4];
    const float* Wv = (const float*)d_in[5];
    const float* bv = (const float*)d_in[6];
    const float* Wo = (const float*)d_in[7];
    const float* bo = (const float*)d_in[8];
    float* out = (float*)d_out;

    float *Qp, *Kp, *Vp, *Ap;
    cudaGetSymbolAddress((void**)&Qp, g_Q);
    cudaGetSymbolAddress((void**)&Kp, g_K);
    cudaGetSymbolAddress((void**)&Vp, g_V);
    cudaGetSymbolAddress((void**)&Ap, g_A);

    dim3 ggrid(NTOT / BN, MTOT / BM);   // (8, 32)
    gemm_nt<1><<<ggrid, 256>>>(x, Wq, bq, Qp);
    gemm_nt<1><<<ggrid, 256>>>(x, Wk, bk, Kp);
    gemm_nt<1><<<ggrid, 256>>>(x, Wv, bv, Vp);

    dim3 agrid(NSEQ / BR, BH);          // (32, 32)
    flash_attn<<<agrid, 256>>>(Qp, Kp, Vp, Ap);

    gemm_nt<0><<<ggrid, 256>>>(Ap, Wo, bo, out);
}

// round 3
// speedup vs baseline: 1.4144x; 1.4144x over previous
#include <cuda_runtime.h>
#include <cuda_bf16.h>
#include <cstddef>
#include <cstdint>

// Problem constants
#define B_SZ   2
#define NSEQ   2048
#define DMODEL 1024
#define NHEAD  16
#define HDIM   64
#define MTOT   (B_SZ * NSEQ)      // 4096
#define BH     (B_SZ * NHEAD)     // 32

// ---------------------------------------------------------------------------
// Scratch (static device arrays; no allocation allowed)
// ---------------------------------------------------------------------------
__device__ __nv_bfloat16 g_xhi[MTOT * DMODEL];
__device__ __nv_bfloat16 g_xlo[MTOT * DMODEL];
__device__ __nv_bfloat16 g_W0hi[DMODEL * DMODEL];
__device__ __nv_bfloat16 g_W0lo[DMODEL * DMODEL];
__device__ __nv_bfloat16 g_W1hi[DMODEL * DMODEL];
__device__ __nv_bfloat16 g_W1lo[DMODEL * DMODEL];
__device__ __nv_bfloat16 g_W2hi[DMODEL * DMODEL];
__device__ __nv_bfloat16 g_W2lo[DMODEL * DMODEL];
__device__ __nv_bfloat16 g_W3hi[DMODEL * DMODEL];
__device__ __nv_bfloat16 g_W3lo[DMODEL * DMODEL];
__device__ __nv_bfloat16 g_Ahi[MTOT * DMODEL];
__device__ __nv_bfloat16 g_Alo[MTOT * DMODEL];
__device__ float g_Q[BH * NSEQ * HDIM];   // [bh, n, hd] fp32
__device__ float g_K[BH * NSEQ * HDIM];
__device__ float g_V[BH * NSEQ * HDIM];

// ---------------------------------------------------------------------------
// PTX helpers (base compute_103 features only: cp.async, ldmatrix, mma.sync)
// ---------------------------------------------------------------------------
__device__ __forceinline__ uint32_t s2u(const void* p) {
    uint32_t r;
    asm("{ .reg .u64 t; cvta.to.shared.u64 t, %1; cvt.u32.u64 %0, t; }" : "=r"(r) : "l"(p));
    return r;
}
__device__ __forceinline__ void cpa16(uint32_t dst, const void* src) {
    asm volatile("cp.async.cg.shared.global [%0], [%1], 16;" :: "r"(dst), "l"(src));
}
__device__ __forceinline__ void ldsm_x4(uint32_t* r, uint32_t addr) {
    asm volatile("ldmatrix.sync.aligned.m8n8.x4.shared.b16 {%0,%1,%2,%3}, [%4];"
                 : "=r"(r[0]), "=r"(r[1]), "=r"(r[2]), "=r"(r[3]) : "r"(addr));
}
__device__ __forceinline__ void mma16816(float* c, const uint32_t* a, const uint32_t* b) {
    asm volatile("mma.sync.aligned.m16n8k16.row.col.f32.bf16.bf16.f32 "
                 "{%0,%1,%2,%3}, {%4,%5,%6,%7}, {%8,%9}, {%0,%1,%2,%3};"
                 : "+f"(c[0]), "+f"(c[1]), "+f"(c[2]), "+f"(c[3])
                 : "r"(a[0]), "r"(a[1]), "r"(a[2]), "r"(a[3]), "r"(b[0]), "r"(b[1]));
}

// bf16 hi/lo split: returns packed hi pair, writes packed lo pair
__device__ __forceinline__ uint32_t pack2_split(float x, float y, uint32_t& lopack) {
    __nv_bfloat16 hx = __float2bfloat16(x);
    __nv_bfloat16 hy = __float2bfloat16(y);
    __nv_bfloat16 lx = __float2bfloat16(x - __bfloat162float(hx));
    __nv_bfloat16 ly = __float2bfloat16(y - __bfloat162float(hy));
    lopack = (uint32_t)__bfloat16_as_ushort(lx) | ((uint32_t)__bfloat16_as_ushort(ly) << 16);
    return (uint32_t)__bfloat16_as_ushort(hx) | ((uint32_t)__bfloat16_as_ushort(hy) << 16);
}

// ---------------------------------------------------------------------------
// fp32 -> bf16 hi/lo split precompute
// ---------------------------------------------------------------------------
__global__ void split_bf16(const float* __restrict__ in,
                           __nv_bfloat16* __restrict__ hi,
                           __nv_bfloat16* __restrict__ lo, int n4)
{
    int i = blockIdx.x * blockDim.x + threadIdx.x;
    if (i >= n4) return;
    float4 v = reinterpret_cast<const float4*>(in)[i];
    uint2 h, l;
    h.x = pack2_split(v.x, v.y, l.x);
    h.y = pack2_split(v.z, v.w, l.y);
    reinterpret_cast<uint2*>(hi)[i] = h;
    reinterpret_cast<uint2*>(lo)[i] = l;
}

// ---------------------------------------------------------------------------
// HMMA bf16-split GEMM:  C[m,n] = sum_k A[m,k]*W[n,k] + bias[n]
// A,W as bf16 hi/lo, K-major [rows][1024].  CTA tile 128x128, K-chunk 32,
// cp.async double buffer, 8 warps in 4x2 (warp tile 32x64), 3 split-MMAs.
// MODE 0: C row-major [MTOT,DMODEL]; MODE 1: scatter to [bh,nseq,hd].
// ---------------------------------------------------------------------------
#define TM 128
#define TN 128
#define KC 32
#define CHUNKS (DMODEL / KC)       // 32
#define TILE_B  8192               // 128 rows x 64 bytes
#define STAGE_B (4 * TILE_B)       // Ahi,Alo,Bhi,Blo
#define GEMM_DSMEM (2 * STAGE_B)   // 64 KB

// Swizzled byte offset within a tile: row in [0,128), chunk = 16B column [0,4)
__device__ __forceinline__ uint32_t swz(uint32_t row, uint32_t chunk) {
    return row * 64u + ((chunk ^ ((row >> 1) & 3u)) << 4);
}

template <int MODE>
__global__ void __launch_bounds__(256, 1)
gemm_tc(const __nv_bfloat16* __restrict__ Ahi, const __nv_bfloat16* __restrict__ Alo,
        const __nv_bfloat16* __restrict__ Bhi, const __nv_bfloat16* __restrict__ Blo,
        const float* __restrict__ bias, float* __restrict__ C)
{
    extern __shared__ char dsm[];
    const uint32_t sbase = s2u(dsm);

    const int tid  = threadIdx.x;
    const int wid  = tid >> 5;
    const int lane = tid & 31;
    const int m0 = blockIdx.y * TM;
    const int n0 = blockIdx.x * TN;
    const int wm = (wid & 3) * 32;     // warp m offset
    const int wn = (wid >> 2) * 64;    // warp n offset

    float acc[2][8][4];
#pragma unroll
    for (int i = 0; i < 2; i++)
#pragma unroll
        for (int j = 0; j < 8; j++)
#pragma unroll
            for (int q = 0; q < 4; q++) acc[i][j][q] = 0.f;

    // load slot for this thread: 2 consecutive 16B chunks (32B) per tile
    const uint32_t lrow = (uint32_t)(tid >> 1);         // 0..127
    const uint32_t lch  = (uint32_t)(tid & 1) * 2;      // 0 or 2

    auto load_chunk = [&](int ch, int s) {
        const uint32_t sb = sbase + (uint32_t)s * STAGE_B;
        const size_t gA = (size_t)(m0 + lrow) * DMODEL + (size_t)ch * KC + lch * 8;
        const size_t gB = (size_t)(n0 + lrow) * DMODEL + (size_t)ch * KC + lch * 8;
#pragma unroll
        for (int c = 0; c < 2; c++) {
            uint32_t so = swz(lrow, lch + c);
            cpa16(sb + 0 * TILE_B + so, Ahi + gA + c * 8);
            cpa16(sb + 1 * TILE_B + so, Alo + gA + c * 8);
            cpa16(sb + 2 * TILE_B + so, Bhi + gB + c * 8);
            cpa16(sb + 3 * TILE_B + so, Blo + gB + c * 8);
        }
        asm volatile("cp.async.commit_group;" ::: "memory");
    };

    load_chunk(0, 0);

    for (int ch = 0; ch < CHUNKS; ++ch) {
        if (ch + 1 < CHUNKS) {
            load_chunk(ch + 1, (ch + 1) & 1);
            asm volatile("cp.async.wait_group 1;" ::: "memory");
        } else {
            asm volatile("cp.async.wait_group 0;" ::: "memory");
        }
        __syncthreads();

        const uint32_t sb = sbase + (uint32_t)(ch & 1) * STAGE_B;
#pragma unroll
        for (int kstep = 0; kstep < 2; kstep++) {
            const uint32_t kc = (uint32_t)kstep * 2;
            uint32_t a_hi[2][4], a_lo[2][4];
#pragma unroll
            for (int mf = 0; mf < 2; mf++) {
                uint32_t row = (uint32_t)(wm + mf * 16 + (lane & 15));
                uint32_t chn = kc + (uint32_t)(lane >> 4);
                ldsm_x4(a_hi[mf], sb + 0 * TILE_B + swz(row, chn));
                ldsm_x4(a_lo[mf], sb + 1 * TILE_B + swz(row, chn));
            }
            uint32_t b_hi[8][2], b_lo[8][2];
#pragma unroll
            for (int nf2 = 0; nf2 < 4; nf2++) {
                uint32_t row = (uint32_t)(wn + nf2 * 16 + 8 * (lane >> 4) + (lane & 7));
                uint32_t chn = kc + (uint32_t)((lane >> 3) & 1);
                uint32_t t[4];
                ldsm_x4(t, sb + 2 * TILE_B + swz(row, chn));
                b_hi[2 * nf2][0] = t[0]; b_hi[2 * nf2][1] = t[1];
                b_hi[2 * nf2 + 1][0] = t[2]; b_hi[2 * nf2 + 1][1] = t[3];
                ldsm_x4(t, sb + 3 * TILE_B + swz(row, chn));
                b_lo[2 * nf2][0] = t[0]; b_lo[2 * nf2][1] = t[1];
                b_lo[2 * nf2 + 1][0] = t[2]; b_lo[2 * nf2 + 1][1] = t[3];
            }
#pragma unroll
            for (int mf = 0; mf < 2; mf++)
#pragma unroll
                for (int nf = 0; nf < 8; nf++) {
                    mma16816(acc[mf][nf], a_hi[mf], b_hi[nf]);
                    mma16816(acc[mf][nf], a_hi[mf], b_lo[nf]);
                    mma16816(acc[mf][nf], a_lo[mf], b_hi[nf]);
                }
        }
        __syncthreads();
    }

    // Epilogue: c-frag mapping, bias add, store float2 pairs
#pragma unroll
    for (int mf = 0; mf < 2; mf++) {
        const int r0 = m0 + wm + mf * 16 + (lane >> 2);
#pragma unroll
        for (int nf = 0; nf < 8; nf++) {
            const int n = n0 + wn + nf * 8 + (lane & 3) * 2;
            const float b0 = bias[n], b1 = bias[n + 1];
            float2 v01 = make_float2(acc[mf][nf][0] + b0, acc[mf][nf][1] + b1);
            float2 v23 = make_float2(acc[mf][nf][2] + b0, acc[mf][nf][3] + b1);
            if (MODE == 0) {
                *reinterpret_cast<float2*>(C + (size_t)r0 * DMODEL + n) = v01;
                *reinterpret_cast<float2*>(C + (size_t)(r0 + 8) * DMODEL + n) = v23;
            } else {
                int h = n >> 6, hd = n & 63;
                int b  = r0 >> 11, ns0 = r0 & 2047;
                *reinterpret_cast<float2*>(
                    g_Q /*unused*/, // placeholder removed below
                    0) ;
            }
        }
    }
    // (MODE==1 path handled separately below to keep the compiler happy)
    if (MODE == 1) { }
}

// Specialized epilogue for MODE 1 requires scatter; re-implement cleanly:
// (We instead provide a second template instantiation path via a functor-free
//  approach: see gemm_tc_scatter below.)

template <int MODE2>
__global__ void __launch_bounds__(256, 1)
gemm_tc2(const __nv_bfloat16* __restrict__ Ahi, const __nv_bfloat16* __restrict__ Alo,
         const __nv_bfloat16* __restrict__ Bhi, const __nv_bfloat16* __restrict__ Blo,
         const float* __restrict__ bias, float* __restrict__ C)
{
    extern __shared__ char dsm[];
    const uint32_t sbase = s2u(dsm);

    const int tid  = threadIdx.x;
    const int wid  = tid >> 5;
    const int lane = tid & 31;
    const int m0 = blockIdx.y * TM;
    const int n0 = blockIdx.x * TN;
    const int wm = (wid & 3) * 32;
    const int wn = (wid >> 2) * 64;

    float acc[2][8][4];
#pragma unroll
    for (int i = 0; i < 2; i++)
#pragma unroll
        for (int j = 0; j < 8; j++)
#pragma unroll
            for (int q = 0; q < 4; q++) acc[i][j][q] = 0.f;

    const uint32_t lrow = (uint32_t)(tid >> 1);
    const uint32_t lch  = (uint32_t)(tid & 1) * 2;

    auto load_chunk = [&](int ch, int s) {
        const uint32_t sb = sbase + (uint32_t)s * STAGE_B;
        const size_t gA = (size_t)(m0 + lrow) * DMODEL + (size_t)ch * KC + lch * 8;
        const size_t gB = (size_t)(n0 + lrow) * DMODEL + (size_t)ch * KC + lch * 8;
#pragma unroll
        for (int c = 0; c < 2; c++) {
            uint32_t so = swz(lrow, lch + c);
            cpa16(sb + 0 * TILE_B + so, Ahi + gA + c * 8);
            cpa16(sb + 1 * TILE_B + so, Alo + gA + c * 8);
            cpa16(sb + 2 * TILE_B + so, Bhi + gB + c * 8);
            cpa16(sb + 3 * TILE_B + so, Blo + gB + c * 8);
        }
        asm volatile("cp.async.commit_group;" ::: "memory");
    };

    load_chunk(0, 0);

    for (int ch = 0; ch < CHUNKS; ++ch) {
        if (ch + 1 < CHUNKS) {
            load_chunk(ch + 1, (ch + 1) & 1);
            asm volatile("cp.async.wait_group 1;" ::: "memory");
        } else {
            asm volatile("cp.async.wait_group 0;" ::: "memory");
        }
        __syncthreads();

        const uint32_t sb = sbase + (uint32_t)(ch & 1) * STAGE_B;
#pragma unroll
        for (int kstep = 0; kstep < 2; kstep++) {
            const uint32_t kc = (uint32_t)kstep * 2;
            uint32_t a_hi[2][4], a_lo[2][4];
#pragma unroll
            for (int mf = 0; mf < 2; mf++) {
                uint32_t row = (uint32_t)(wm + mf * 16 + (lane & 15));
                uint32_t chn = kc + (uint32_t)(lane >> 4);
                ldsm_x4(a_hi[mf], sb + 0 * TILE_B + swz(row, chn));
                ldsm_x4(a_lo[mf], sb + 1 * TILE_B + swz(row, chn));
            }
            uint32_t b_hi[8][2], b_lo[8][2];
#pragma unroll
            for (int nf2 = 0; nf2 < 4; nf2++) {
                uint32_t row = (uint32_t)(wn + nf2 * 16 + 8 * (lane >> 4) + (lane & 7));
                uint32_t chn = kc + (uint32_t)((lane >> 3) & 1);
                uint32_t t[4];
                ldsm_x4(t, sb + 2 * TILE_B + swz(row, chn));
                b_hi[2 * nf2][0] = t[0]; b_hi[2 * nf2][1] = t[1];
                b_hi[2 * nf2 + 1][0] = t[2]; b_hi[2 * nf2 + 1][1] = t[3];
                ldsm_x4(t, sb + 3 * TILE_B + swz(row, chn));
                b_lo[2 * nf2][0] = t[0]; b_lo[2 * nf2][1] = t[1];
                b_lo[2 * nf2 + 1][0] = t[2]; b_lo[2 * nf2 + 1][1] = t[3];
            }
#pragma unroll
            for (int mf = 0; mf < 2; mf++)
#pragma unroll
                for (int nf = 0; nf < 8; nf++) {
                    mma16816(acc[mf][nf], a_hi[mf], b_hi[nf]);
                    mma16816(acc[mf][nf], a_hi[mf], b_lo[nf]);
                    mma16816(acc[mf][nf], a_lo[mf], b_hi[nf]);
                }
        }
        __syncthreads();
    }

#pragma unroll
    for (int mf = 0; mf < 2; mf++) {
        const int rbase = m0 + wm + mf * 16 + (lane >> 2);
#pragma unroll
        for (int nf = 0; nf < 8; nf++) {
            const int n = n0 + wn + nf * 8 + (lane & 3) * 2;
            const float b0 = bias[n], b1 = bias[n + 1];
#pragma unroll
            for (int half = 0; half < 2; half++) {
                const int m = rbase + half * 8;
                float2 v = make_float2(acc[mf][nf][2 * half] + b0,
                                       acc[mf][nf][2 * half + 1] + b1);
                if (MODE2 == 0) {
                    *reinterpret_cast<float2*>(C + (size_t)m * DMODEL + n) = v;
                } else {
                    int h = n >> 6, hd = n & 63;
                    int b  = m >> 11, ns = m & 2047;
                    *reinterpret_cast<float2*>(
                        C + (((size_t)(b * NHEAD + h) * NSEQ) + ns) * HDIM + hd) = v;
                }
            }
        }
    }
}

// ---------------------------------------------------------------------------
// Fused flash attention (fp32), vectorized smem access.
// Q,K,V: [BH, NSEQ, 64]. Output written as bf16 hi/lo split in [B,N,D] layout.
// ---------------------------------------------------------------------------
#define BR 64
#define BC 32

__global__ void __launch_bounds__(256, 4)
flash_attn(const float* __restrict__ Q, const float* __restrict__ K,
           const float* __restrict__ V,
           __nv_bfloat16* __restrict__ Ohi, __nv_bfloat16* __restrict__ Olo)
{
    __shared__ float QsT[64][68];
    __shared__ float KsT[64][34];
    __shared__ float Vs[32][64];
    __shared__ float PsT[32][68];

    const int tid = threadIdx.x;
    const int tx  = tid & 15;
    const int ty  = tid >> 4;
    const int bh  = blockIdx.y;
    const int q0  = blockIdx.x * BR;

    const float* Qb = Q + (size_t)bh * NSEQ * HDIM;
    const float* Kb = K + (size_t)bh * NSEQ * HDIM;
    const float* Vb = V + (size_t)bh * NSEQ * HDIM;

#pragma unroll
    for (int it = 0; it < 4; it++) {
        int idx = tid * 4 + it;
        int r   = idx >> 4;
        int c4  = (idx & 15) * 4;
        float4 v = *(const float4*)(Qb + (size_t)(q0 + r) * HDIM + c4);
        QsT[c4 + 0][r] = v.x * 0.125f;
        QsT[c4 + 1][r] = v.y * 0.125f;
        QsT[c4 + 2][r] = v.z * 0.125f;
        QsT[c4 + 3][r] = v.w * 0.125f;
    }

    float o[4][4];
    float mI[4], lI[4];
#pragma unroll
    for (int i = 0; i < 4; i++) {
        mI[i] = -1e30f; lI[i] = 0.f;
#pragma unroll
        for (int j = 0; j < 4; j++) o[i][j] = 0.f;
    }
    const int r0 = ty * 4;

    for (int kt = 0; kt < NSEQ / BC; kt++) {
        __syncthreads();
#pragma unroll
        for (int it = 0; it < 2; it++) {
            int idx = tid * 2 + it;
            int r   = idx >> 4;
            int c4  = (idx & 15) * 4;
            float4 vk = *(const float4*)(Kb + (size_t)(kt * BC + r) * HDIM + c4);
            KsT[c4 + 0][r] = vk.x; KsT[c4 + 1][r] = vk.y;
            KsT[c4 + 2][r] = vk.z; KsT[c4 + 3][r] = vk.w;
            float4 vv = *(const float4*)(Vb + (size_t)(kt * BC + r) * HDIM + c4);
            *(float4*)(&Vs[r][c4]) = vv;
        }
        __syncthreads();

        float s0[4], s1[4];
#pragma unroll
        for (int i = 0; i < 4; i++) { s0[i] = 0.f; s1[i] = 0.f; }
        const int c0s = tx * 2;
#pragma unroll
        for (int k = 0; k < 64; k++) {
            float4 a = *(const float4*)(&QsT[k][r0]);
            float2 b = *(const float2*)(&KsT[k][c0s]);
            s0[0] += a.x * b.x; s1[0] += a.x * b.y;
            s0[1] += a.y * b.x; s1[1] += a.y * b.y;
            s0[2] += a.z * b.x; s1[2] += a.z * b.y;
            s0[3] += a.w * b.x; s1[3] += a.w * b.y;
        }

#pragma unroll
        for (int i = 0; i < 4; i++) {
            float mx = fmaxf(s0[i], s1[i]);
#pragma unroll
            for (int off = 1; off < 16; off <<= 1)
                mx = fmaxf(mx, __shfl_xor_sync(0xffffffffu, mx, off));
            float mnew = fmaxf(mI[i], mx);
            float p0 = __expf(s0[i] - mnew);
            float p1 = __expf(s1[i] - mnew);
            float sum = p0 + p1;
#pragma unroll
            for (int off = 1; off < 16; off <<= 1)
                sum += __shfl_xor_sync(0xffffffffu, sum, off);
            float alpha = __expf(mI[i] - mnew);
            lI[i] = lI[i] * alpha + sum;
            mI[i] = mnew;
#pragma unroll
            for (int j = 0; j < 4; j++) o[i][j] *= alpha;
            PsT[c0s + 0][r0 + i] = p0;
            PsT[c0s + 1][r0 + i] = p1;
        }
        __syncthreads();

        const int c0v = tx * 4;
#pragma unroll
        for (int kc = 0; kc < 32; kc++) {
            float4 a = *(const float4*)(&PsT[kc][r0]);
            float4 b = *(const float4*)(&Vs[kc][c0v]);
            o[0][0] += a.x * b.x; o[0][1] += a.x * b.y; o[0][2] += a.x * b.z; o[0][3] += a.x * b.w;
            o[1][0] += a.y * b.x; o[1][1] += a.y * b.y; o[1][2] += a.y * b.z; o[1][3] += a.y * b.w;
            o[2][0] += a.z * b.x; o[2][1] += a.z * b.y; o[2][2] += a.z * b.z; o[2][3] += a.z * b.w;
            o[3][0] += a.w * b.x; o[3][1] += a.w * b.y; o[3][2] += a.w * b.z; o[3][3] += a.w * b.w;
        }
    }

    const int bb = bh >> 4;
    const int h  = bh & 15;
#pragma unroll
    for (int i = 0; i < 4; i++) {
        float inv = 1.f / lI[i];
        int q = q0 + r0 + i;
        float v0 = o[i][0] * inv, v1 = o[i][1] * inv;
        float v2 = o[i][2] * inv, v3 = o[i][3] * inv;
        uint2 hp, lp;
        hp.x = pack2_split(v0, v1, lp.x);
        hp.y = pack2_split(v2, v3, lp.y);
        size_t base = ((size_t)(bb * NSEQ + q)) * DMODEL + h * HDIM + tx * 4;
        *reinterpret_cast<uint2*>(Ohi + base) = hp;
        *reinterpret_cast<uint2*>(Olo + base) = lp;
    }
}

// ---------------------------------------------------------------------------
// Launch
// ---------------------------------------------------------------------------
extern "C" void kernel_launch(void* const* d_in, const int* in_sizes, int n_in,
                              void* d_out, int out_size)
{
    const float* x  = (const float*)d_in[0];
    const float* Wq = (const float*)d_in[1];
    const float* bq = (const float*)d_in[2];
    const float* Wk = (const float*)d_in[3];
    const float* bk = (const float*)d_in[4];
    const float* Wv = (const float*)d_in[5];
    const float* bv = (const float*)d_in[6];
    const float* Wo = (const float*)d_in[7];
    const float* bo = (const float*)d_in[8];
    float* out = (float*)d_out;

    __nv_bfloat16 *xhi, *xlo, *w0h, *w0l, *w1h, *w1l, *w2h, *w2l, *w3h, *w3l, *ahi, *alo;
    float *Qp, *Kp, *Vp;
    cudaGetSymbolAddress((void**)&xhi, g_xhi);  cudaGetSymbolAddress((void**)&xlo, g_xlo);
    cudaGetSymbolAddress((void**)&w0h, g_W0hi); cudaGetSymbolAddress((void**)&w0l, g_W0lo);
    cudaGetSymbolAddress((void**)&w1h, g_W1hi); cudaGetSymbolAddress((void**)&w1l, g_W1lo);
    cudaGetSymbolAddress((void**)&w2h, g_W2hi); cudaGetSymbolAddress((void**)&w2l, g_W2lo);
    cudaGetSymbolAddress((void**)&w3h, g_W3hi); cudaGetSymbolAddress((void**)&w3l, g_W3lo);
    cudaGetSymbolAddress((void**)&ahi, g_Ahi);  cudaGetSymbolAddress((void**)&alo, g_Alo);
    cudaGetSymbolAddress((void**)&Qp, g_Q);
    cudaGetSymbolAddress((void**)&Kp, g_K);
    cudaGetSymbolAddress((void**)&Vp, g_V);

    cudaFuncSetAttribute(gemm_tc2<0>, cudaFuncAttributeMaxDynamicSharedMemorySize, GEMM_DSMEM);
    cudaFuncSetAttribute(gemm_tc2<1>, cudaFuncAttributeMaxDynamicSharedMemorySize, GEMM_DSMEM);

    split_bf16<<<MTOT * DMODEL / 4 / 256, 256>>>(x,  xhi, xlo, MTOT * DMODEL / 4);
    split_bf16<<<DMODEL * DMODEL / 4 / 256, 256>>>(Wq, w0h, w0l, DMODEL * DMODEL / 4);
    split_bf16<<<DMODEL * DMODEL / 4 / 256, 256>>>(Wk, w1h, w1l, DMODEL * DMODEL / 4);
    split_bf16<<<DMODEL * DMODEL / 4 / 256, 256>>>(Wv, w2h, w2l, DMODEL * DMODEL / 4);
    split_bf16<<<DMODEL * DMODEL / 4 / 256, 256>>>(Wo, w3h, w3l, DMODEL * DMODEL / 4);

    dim3 ggrid(DMODEL / TN, MTOT / TM);   // (8, 32)
    gemm_tc2<1><<<ggrid, 256, GEMM_DSMEM>>>(xhi, xlo, w0h, w0l, bq, Qp);
    gemm_tc2<1><<<ggrid, 256, GEMM_DSMEM>>>(xhi, xlo, w1h, w1l, bk, Kp);
    gemm_tc2<1><<<ggrid, 256, GEMM_DSMEM>>>(xhi, xlo, w2h, w2l, bv, Vp);

    dim3 agrid(NSEQ / BR, BH);            // (32, 32)
    flash_attn<<<agrid, 256>>>(Qp, Kp, Vp, ahi, alo);

    gemm_tc2<0><<<ggrid, 256, GEMM_DSMEM>>>(ahi, alo, w3h, w3l, bo, out);
}

// round 4
// speedup vs baseline: 2.9130x; 2.0595x over previous
#include <cuda_runtime.h>
#include <cuda_bf16.h>
#include <cstddef>
#include <cstdint>

// Problem constants
#define B_SZ   2
#define NSEQ   2048
#define DMODEL 1024
#define NHEAD  16
#define HDIM   64
#define MTOT   (B_SZ * NSEQ)      // 4096
#define BH     (B_SZ * NHEAD)     // 32

// ---------------------------------------------------------------------------
// Scratch (static device arrays; no allocation allowed)
// ---------------------------------------------------------------------------
__device__ __nv_bfloat16 g_xhi[MTOT * DMODEL];
__device__ __nv_bfloat16 g_xlo[MTOT * DMODEL];
__device__ __nv_bfloat16 g_W0hi[DMODEL * DMODEL];
__device__ __nv_bfloat16 g_W0lo[DMODEL * DMODEL];
__device__ __nv_bfloat16 g_W1hi[DMODEL * DMODEL];
__device__ __nv_bfloat16 g_W1lo[DMODEL * DMODEL];
__device__ __nv_bfloat16 g_W2hi[DMODEL * DMODEL];
__device__ __nv_bfloat16 g_W2lo[DMODEL * DMODEL];
__device__ __nv_bfloat16 g_W3hi[DMODEL * DMODEL];
__device__ __nv_bfloat16 g_W3lo[DMODEL * DMODEL];
__device__ __nv_bfloat16 g_Ahi[MTOT * DMODEL];
__device__ __nv_bfloat16 g_Alo[MTOT * DMODEL];
// QKV in bf16 hi/lo, [bh][n][64]
__device__ __nv_bfloat16 g_Qhi[BH * NSEQ * HDIM];
__device__ __nv_bfloat16 g_Qlo[BH * NSEQ * HDIM];
__device__ __nv_bfloat16 g_Khi[BH * NSEQ * HDIM];
__device__ __nv_bfloat16 g_Klo[BH * NSEQ * HDIM];
__device__ __nv_bfloat16 g_Vhi[BH * NSEQ * HDIM];
__device__ __nv_bfloat16 g_Vlo[BH * NSEQ * HDIM];

// ---------------------------------------------------------------------------
// PTX helpers (base compute_103: cp.async, ldmatrix, mma.sync)
// ---------------------------------------------------------------------------
__device__ __forceinline__ uint32_t s2u(const void* p) {
    uint32_t r;
    asm("{ .reg .u64 t; cvta.to.shared.u64 t, %1; cvt.u32.u64 %0, t; }" : "=r"(r) : "l"(p));
    return r;
}
__device__ __forceinline__ void cpa16(uint32_t dst, const void* src) {
    asm volatile("cp.async.cg.shared.global [%0], [%1], 16;" :: "r"(dst), "l"(src));
}
__device__ __forceinline__ void ldsm_x4(uint32_t* r, uint32_t addr) {
    asm volatile("ldmatrix.sync.aligned.m8n8.x4.shared.b16 {%0,%1,%2,%3}, [%4];"
                 : "=r"(r[0]), "=r"(r[1]), "=r"(r[2]), "=r"(r[3]) : "r"(addr));
}
__device__ __forceinline__ void ldsm_x4_t(uint32_t* r, uint32_t addr) {
    asm volatile("ldmatrix.sync.aligned.m8n8.x4.trans.shared.b16 {%0,%1,%2,%3}, [%4];"
                 : "=r"(r[0]), "=r"(r[1]), "=r"(r[2]), "=r"(r[3]) : "r"(addr));
}
__device__ __forceinline__ void mma16816(float* c, const uint32_t* a, const uint32_t* b) {
    asm volatile("mma.sync.aligned.m16n8k16.row.col.f32.bf16.bf16.f32 "
                 "{%0,%1,%2,%3}, {%4,%5,%6,%7}, {%8,%9}, {%0,%1,%2,%3};"
                 : "+f"(c[0]), "+f"(c[1]), "+f"(c[2]), "+f"(c[3])
                 : "r"(a[0]), "r"(a[1]), "r"(a[2]), "r"(a[3]), "r"(b[0]), "r"(b[1]));
}

// bf16 hi/lo split: returns packed hi pair, writes packed lo pair
__device__ __forceinline__ uint32_t pack2_split(float x, float y, uint32_t& lopack) {
    __nv_bfloat16 hx = __float2bfloat16(x);
    __nv_bfloat16 hy = __float2bfloat16(y);
    __nv_bfloat16 lx = __float2bfloat16(x - __bfloat162float(hx));
    __nv_bfloat16 ly = __float2bfloat16(y - __bfloat162float(hy));
    lopack = (uint32_t)__bfloat16_as_ushort(lx) | ((uint32_t)__bfloat16_as_ushort(ly) << 16);
    return (uint32_t)__bfloat16_as_ushort(hx) | ((uint32_t)__bfloat16_as_ushort(hy) << 16);
}

// ---------------------------------------------------------------------------
// fp32 -> bf16 hi/lo split precompute
// ---------------------------------------------------------------------------
__global__ void split_bf16(const float* __restrict__ in,
                           __nv_bfloat16* __restrict__ hi,
                           __nv_bfloat16* __restrict__ lo, int n4)
{
    int i = blockIdx.x * blockDim.x + threadIdx.x;
    if (i >= n4) return;
    float4 v = reinterpret_cast<const float4*>(in)[i];
    uint2 h, l;
    h.x = pack2_split(v.x, v.y, l.x);
    h.y = pack2_split(v.z, v.w, l.y);
    reinterpret_cast<uint2*>(hi)[i] = h;
    reinterpret_cast<uint2*>(lo)[i] = l;
}

// ---------------------------------------------------------------------------
// HMMA bf16-split GEMM:  C[m,n] = (sum_k A[m,k]*W[n,k] + bias[n]) * scale
// MODE 0: fp32 C row-major [MTOT,DMODEL]
// MODE 1: bf16 hi/lo scatter to [bh][nseq][hd]
// ---------------------------------------------------------------------------
#define TM 128
#define TN 128
#define KC 32
#define CHUNKS (DMODEL / KC)       // 32
#define TILE_B  8192               // 128 rows x 64 bytes
#define STAGE_B (4 * TILE_B)
#define GEMM_DSMEM (2 * STAGE_B)   // 64 KB

__device__ __forceinline__ uint32_t swz(uint32_t row, uint32_t chunk) {
    return row * 64u + ((chunk ^ ((row >> 1) & 3u)) << 4);
}

template <int MODE>
__global__ void __launch_bounds__(256, 1)
gemm_tc2(const __nv_bfloat16* __restrict__ Ahi, const __nv_bfloat16* __restrict__ Alo,
         const __nv_bfloat16* __restrict__ Bhi, const __nv_bfloat16* __restrict__ Blo,
         const float* __restrict__ bias, float* __restrict__ C,
         __nv_bfloat16* __restrict__ Chi, __nv_bfloat16* __restrict__ Clo,
         float scale)
{
    extern __shared__ char dsm[];
    const uint32_t sbase = s2u(dsm);

    const int tid  = threadIdx.x;
    const int wid  = tid >> 5;
    const int lane = tid & 31;
    const int m0 = blockIdx.y * TM;
    const int n0 = blockIdx.x * TN;
    const int wm = (wid & 3) * 32;
    const int wn = (wid >> 2) * 64;

    float acc[2][8][4];
#pragma unroll
    for (int i = 0; i < 2; i++)
#pragma unroll
        for (int j = 0; j < 8; j++)
#pragma unroll
            for (int q = 0; q < 4; q++) acc[i][j][q] = 0.f;

    const uint32_t lrow = (uint32_t)(tid >> 1);
    const uint32_t lch  = (uint32_t)(tid & 1) * 2;

    auto load_chunk = [&](int ch, int s) {
        const uint32_t sb = sbase + (uint32_t)s * STAGE_B;
        const size_t gA = (size_t)(m0 + lrow) * DMODEL + (size_t)ch * KC + lch * 8;
        const size_t gB = (size_t)(n0 + lrow) * DMODEL + (size_t)ch * KC + lch * 8;
#pragma unroll
        for (int c = 0; c < 2; c++) {
            uint32_t so = swz(lrow, lch + c);
            cpa16(sb + 0 * TILE_B + so, Ahi + gA + c * 8);
            cpa16(sb + 1 * TILE_B + so, Alo + gA + c * 8);
            cpa16(sb + 2 * TILE_B + so, Bhi + gB + c * 8);
            cpa16(sb + 3 * TILE_B + so, Blo + gB + c * 8);
        }
        asm volatile("cp.async.commit_group;" ::: "memory");
    };

    load_chunk(0, 0);

    for (int ch = 0; ch < CHUNKS; ++ch) {
        if (ch + 1 < CHUNKS) {
            load_chunk(ch + 1, (ch + 1) & 1);
            asm volatile("cp.async.wait_group 1;" ::: "memory");
        } else {
            asm volatile("cp.async.wait_group 0;" ::: "memory");
        }
        __syncthreads();

        const uint32_t sb = sbase + (uint32_t)(ch & 1) * STAGE_B;
#pragma unroll
        for (int kstep = 0; kstep < 2; kstep++) {
            const uint32_t kc = (uint32_t)kstep * 2;
            uint32_t a_hi[2][4], a_lo[2][4];
#pragma unroll
            for (int mf = 0; mf < 2; mf++) {
                uint32_t row = (uint32_t)(wm + mf * 16 + (lane & 15));
                uint32_t chn = kc + (uint32_t)(lane >> 4);
                ldsm_x4(a_hi[mf], sb + 0 * TILE_B + swz(row, chn));
                ldsm_x4(a_lo[mf], sb + 1 * TILE_B + swz(row, chn));
            }
            uint32_t b_hi[8][2], b_lo[8][2];
#pragma unroll
            for (int nf2 = 0; nf2 < 4; nf2++) {
                uint32_t row = (uint32_t)(wn + nf2 * 16 + 8 * (lane >> 4) + (lane & 7));
                uint32_t chn = kc + (uint32_t)((lane >> 3) & 1);
                uint32_t t[4];
                ldsm_x4(t, sb + 2 * TILE_B + swz(row, chn));
                b_hi[2 * nf2][0] = t[0]; b_hi[2 * nf2][1] = t[1];
                b_hi[2 * nf2 + 1][0] = t[2]; b_hi[2 * nf2 + 1][1] = t[3];
                ldsm_x4(t, sb + 3 * TILE_B + swz(row, chn));
                b_lo[2 * nf2][0] = t[0]; b_lo[2 * nf2][1] = t[1];
                b_lo[2 * nf2 + 1][0] = t[2]; b_lo[2 * nf2 + 1][1] = t[3];
            }
#pragma unroll
            for (int mf = 0; mf < 2; mf++)
#pragma unroll
                for (int nf = 0; nf < 8; nf++) {
                    mma16816(acc[mf][nf], a_hi[mf], b_hi[nf]);
                    mma16816(acc[mf][nf], a_hi[mf], b_lo[nf]);
                    mma16816(acc[mf][nf], a_lo[mf], b_hi[nf]);
                }
        }
        __syncthreads();
    }

#pragma unroll
    for (int mf = 0; mf < 2; mf++) {
        const int rbase = m0 + wm + mf * 16 + (lane >> 2);
#pragma unroll
        for (int nf = 0; nf < 8; nf++) {
            const int n = n0 + wn + nf * 8 + (lane & 3) * 2;
            const float b0 = bias[n], b1 = bias[n + 1];
#pragma unroll
            for (int half = 0; half < 2; half++) {
                const int m = rbase + half * 8;
                float v0 = (acc[mf][nf][2 * half] + b0) * scale;
                float v1 = (acc[mf][nf][2 * half + 1] + b1) * scale;
                if (MODE == 0) {
                    *reinterpret_cast<float2*>(C + (size_t)m * DMODEL + n) =
                        make_float2(v0, v1);
                } else {
                    int h = n >> 6, hd = n & 63;
                    int b  = m >> 11, ns = m & 2047;
                    size_t idx = (((size_t)(b * NHEAD + h) * NSEQ) + ns) * HDIM + hd;
                    uint32_t lp, hp = pack2_split(v0, v1, lp);
                    *reinterpret_cast<uint32_t*>(Chi + idx) = hp;
                    *reinterpret_cast<uint32_t*>(Clo + idx) = lp;
                }
            }
        }
    }
}

// ---------------------------------------------------------------------------
// HMMA flash attention, bf16-split.  Q/K/V: bf16 hi/lo [bh][n][64].
// CTA: 128 q-rows x 64 kv per iteration, 8 warps (16 q-rows each).
// Online softmax in accumulator registers; P·V reuses acc layout as A-frags.
// Output: bf16 hi/lo in [B,N,D] layout (feeds O projection).
// ---------------------------------------------------------------------------
#define FBR 128
#define FBC 64
#define FKT (NSEQ / FBC)          // 32
// smem: Q hi/lo 2x16KB, then 2 stages x (Khi,Klo,Vhi,Vlo each 8KB)
#define FQHI 0
#define FQLO 16384
#define FSTG0 32768
#define FSTG_B 32768
#define FLASH_DSMEM (32768 + 2 * FSTG_B)   // 96 KB

__device__ __forceinline__ uint32_t swz8(uint32_t row, uint32_t chunk) {
    return row * 128u + ((chunk ^ (row & 7u)) << 4);
}

__global__ void __launch_bounds__(256, 1)
flash_mma(const __nv_bfloat16* __restrict__ Qhi, const __nv_bfloat16* __restrict__ Qlo,
          const __nv_bfloat16* __restrict__ Khi, const __nv_bfloat16* __restrict__ Klo,
          const __nv_bfloat16* __restrict__ Vhi, const __nv_bfloat16* __restrict__ Vlo,
          __nv_bfloat16* __restrict__ Ohi, __nv_bfloat16* __restrict__ Olo)
{
    extern __shared__ char fsm[];
    const uint32_t sbase = s2u(fsm);

    const int tid  = threadIdx.x;
    const int wid  = tid >> 5;
    const int lane = tid & 31;
    const int bh   = blockIdx.y;
    const int q0   = blockIdx.x * FBR;

    const size_t hb = (size_t)bh * NSEQ * HDIM;
    const __nv_bfloat16* Qh = Qhi + hb; const __nv_bfloat16* Ql = Qlo + hb;
    const __nv_bfloat16* Kh = Khi + hb; const __nv_bfloat16* Kl = Klo + hb;
    const __nv_bfloat16* Vh = Vhi + hb; const __nv_bfloat16* Vl = Vlo + hb;

    // ---- Q tile load (once): 128 rows x 8 chunks, hi+lo
    {
        const uint32_t row = (uint32_t)(tid >> 1);
        const uint32_t c0  = (uint32_t)(tid & 1) * 4;
        const size_t g = (size_t)(q0 + row) * HDIM + c0 * 8;
#pragma unroll
        for (int c = 0; c < 4; c++) {
            uint32_t sw = swz8(row, c0 + c);
            cpa16(sbase + FQHI + sw, Qh + g + c * 8);
            cpa16(sbase + FQLO + sw, Ql + g + c * 8);
        }
    }
    // ---- K/V stage load
    auto load_kv = [&](int kt, int s) {
        const uint32_t sb = sbase + FSTG0 + (uint32_t)s * FSTG_B;
        const uint32_t row = (uint32_t)(tid >> 2);
        const uint32_t cc  = (uint32_t)(tid & 3) * 2;
        const size_t g = (size_t)(kt * FBC + row) * HDIM + cc * 8;
#pragma unroll
        for (int j = 0; j < 2; j++) {
            uint32_t sw = swz8(row, cc + j);
            cpa16(sb +     0u + sw, Kh + g + j * 8);
            cpa16(sb +  8192u + sw, Kl + g + j * 8);
            cpa16(sb + 16384u + sw, Vh + g + j * 8);
            cpa16(sb + 24576u + sw, Vl + g + j * 8);
        }
        asm volatile("cp.async.commit_group;" ::: "memory");
    };
    load_kv(0, 0);   // group also carries Q

    // per-thread state
    float o[8][4];
#pragma unroll
    for (int j = 0; j < 8; j++)
#pragma unroll
        for (int q = 0; q < 4; q++) o[j][q] = 0.f;
    float m0s = -1e30f, m1s = -1e30f, l0s = 0.f, l1s = 0.f;
    uint32_t aQh[4][4], aQl[4][4];

    // lane-derived fragment address components
    const uint32_t la15 = (uint32_t)(lane & 15);
    const uint32_t la7  = (uint32_t)(lane & 7);
    const uint32_t lb8  = 8u * (uint32_t)(lane >> 4);          // B-style row add
    const uint32_t lbc  = (uint32_t)((lane >> 3) & 1);         // B-style chunk add
    const uint32_t lac  = (uint32_t)(lane >> 4);               // A-style chunk add

    for (int kt = 0; kt < FKT; kt++) {
        if (kt + 1 < FKT) load_kv(kt + 1, (kt + 1) & 1);
        if (kt + 1 < FKT) { asm volatile("cp.async.wait_group 1;" ::: "memory"); }
        else              { asm volatile("cp.async.wait_group 0;" ::: "memory"); }
        __syncthreads();

        if (kt == 0) {
            // load Q fragments (A-style): rows wid*16 + (lane&15), chunk 2kf + lane>>4
#pragma unroll
            for (int kf = 0; kf < 4; kf++) {
                uint32_t ad = swz8((uint32_t)(wid * 16) + la15, 2u * kf + lac);
                ldsm_x4(aQh[kf], sbase + FQHI + ad);
                ldsm_x4(aQl[kf], sbase + FQLO + ad);
            }
        }

        const uint32_t sb = sbase + FSTG0 + (uint32_t)(kt & 1) * FSTG_B;
        float acc[8][4];
#pragma unroll
        for (int j = 0; j < 8; j++)
#pragma unroll
            for (int q = 0; q < 4; q++) acc[j][q] = 0.f;

        // ---- S = Q K^T : B-frags from K (B-style address)
#pragma unroll
        for (int kf = 0; kf < 4; kf++) {
#pragma unroll
            for (int np = 0; np < 4; np++) {
                uint32_t ad = swz8((uint32_t)(np * 16) + la7 + lb8, 2u * kf + lbc);
                uint32_t kh[4], kl[4];
                ldsm_x4(kh, sb + 0u + ad);
                ldsm_x4(kl, sb + 8192u + ad);
                uint32_t b0h[2] = {kh[0], kh[1]}, b1h[2] = {kh[2], kh[3]};
                uint32_t b0l[2] = {kl[0], kl[1]}, b1l[2] = {kl[2], kl[3]};
                mma16816(acc[2 * np],     aQh[kf], b0h);
                mma16816(acc[2 * np + 1], aQh[kf], b1h);
                mma16816(acc[2 * np],     aQh[kf], b0l);
                mma16816(acc[2 * np + 1], aQh[kf], b1l);
                mma16816(acc[2 * np],     aQl[kf], b0h);
                mma16816(acc[2 * np + 1], aQl[kf], b1h);
            }
        }

        // ---- online softmax (rows: lane>>2 and lane>>2 + 8; quad = 4 lanes)
        float mx0 = -1e30f, mx1 = -1e30f;
#pragma unroll
        for (int nf = 0; nf < 8; nf++) {
            mx0 = fmaxf(mx0, fmaxf(acc[nf][0], acc[nf][1]));
            mx1 = fmaxf(mx1, fmaxf(acc[nf][2], acc[nf][3]));
        }
        mx0 = fmaxf(mx0, __shfl_xor_sync(0xffffffffu, mx0, 1));
        mx0 = fmaxf(mx0, __shfl_xor_sync(0xffffffffu, mx0, 2));
        mx1 = fmaxf(mx1, __shfl_xor_sync(0xffffffffu, mx1, 1));
        mx1 = fmaxf(mx1, __shfl_xor_sync(0xffffffffu, mx1, 2));
        float mn0 = fmaxf(m0s, mx0), mn1 = fmaxf(m1s, mx1);
        float al0 = __expf(m0s - mn0), al1 = __expf(m1s - mn1);
        m0s = mn0; m1s = mn1;
        float sum0 = 0.f, sum1 = 0.f;
#pragma unroll
        for (int nf = 0; nf < 8; nf++) {
            acc[nf][0] = __expf(acc[nf][0] - mn0);
            acc[nf][1] = __expf(acc[nf][1] - mn0);
            acc[nf][2] = __expf(acc[nf][2] - mn1);
            acc[nf][3] = __expf(acc[nf][3] - mn1);
            sum0 += acc[nf][0] + acc[nf][1];
            sum1 += acc[nf][2] + acc[nf][3];
        }
        sum0 += __shfl_xor_sync(0xffffffffu, sum0, 1);
        sum0 += __shfl_xor_sync(0xffffffffu, sum0, 2);
        sum1 += __shfl_xor_sync(0xffffffffu, sum1, 1);
        sum1 += __shfl_xor_sync(0xffffffffu, sum1, 2);
        l0s = l0s * al0 + sum0;
        l1s = l1s * al1 + sum1;
#pragma unroll
        for (int nf = 0; nf < 8; nf++) {
            o[nf][0] *= al0; o[nf][1] *= al0;
            o[nf][2] *= al1; o[nf][3] *= al1;
        }
        // ---- pack P into A-frags (kf over kv16): a0..a3 from acc pairs
        uint32_t pH[4][4], pL[4][4];
#pragma unroll
        for (int kf = 0; kf < 4; kf++) {
            pH[kf][0] = pack2_split(acc[2 * kf][0],     acc[2 * kf][1],     pL[kf][0]);
            pH[kf][1] = pack2_split(acc[2 * kf][2],     acc[2 * kf][3],     pL[kf][1]);
            pH[kf][2] = pack2_split(acc[2 * kf + 1][0], acc[2 * kf + 1][1], pL[kf][2]);
            pH[kf][3] = pack2_split(acc[2 * kf + 1][2], acc[2 * kf + 1][3], pL[kf][3]);
        }

        // ---- O += P V : B-frags from V via ldmatrix.trans (A-style address)
#pragma unroll
        for (int kf = 0; kf < 4; kf++) {
#pragma unroll
            for (int dp = 0; dp < 4; dp++) {
                uint32_t ad = swz8((uint32_t)(kf * 16) + la15, 2u * dp + lac);
                uint32_t vh[4], vl[4];
                ldsm_x4_t(vh, sb + 16384u + ad);
                ldsm_x4_t(vl, sb + 24576u + ad);
                uint32_t bh0[2] = {vh[0], vh[1]}, bh1[2] = {vh[2], vh[3]};
                uint32_t bl0[2] = {vl[0], vl[1]}, bl1[2] = {vl[2], vl[3]};
                mma16816(o[2 * dp],     pH[kf], bh0);
                mma16816(o[2 * dp + 1], pH[kf], bh1);
                mma16816(o[2 * dp],     pH[kf], bl0);
                mma16816(o[2 * dp + 1], pH[kf], bl1);
                mma16816(o[2 * dp],     pL[kf], bh0);
                mma16816(o[2 * dp + 1], pL[kf], bh1);
            }
        }
        __syncthreads();
    }

    // ---- normalize + write bf16 hi/lo to [B,N,D]
    const int bb = bh >> 4;
    const int h  = bh & 15;
    const float inv0 = 1.f / l0s, inv1 = 1.f / l1s;
    const int qlo = q0 + wid * 16 + (lane >> 2);
#pragma unroll
    for (int nf = 0; nf < 8; nf++) {
        const int gcol = h * HDIM + nf * 8 + (lane & 3) * 2;
        uint32_t lp, hp;
        hp = pack2_split(o[nf][0] * inv0, o[nf][1] * inv0, lp);
        size_t i0 = ((size_t)(bb * NSEQ + qlo)) * DMODEL + gcol;
        *reinterpret_cast<uint32_t*>(Ohi + i0) = hp;
        *reinterpret_cast<uint32_t*>(Olo + i0) = lp;
        hp = pack2_split(o[nf][2] * inv1, o[nf][3] * inv1, lp);
        size_t i1 = ((size_t)(bb * NSEQ + qlo + 8)) * DMODEL + gcol;
        *reinterpret_cast<uint32_t*>(Ohi + i1) = hp;
        *reinterpret_cast<uint32_t*>(Olo + i1) = lp;
    }
}

// ---------------------------------------------------------------------------
// Launch
// ---------------------------------------------------------------------------
extern "C" void kernel_launch(void* const* d_in, const int* in_sizes, int n_in,
                              void* d_out, int out_size)
{
    const float* x  = (const float*)d_in[0];
    const float* Wq = (const float*)d_in[1];
    const float* bq = (const float*)d_in[2];
    const float* Wk = (const float*)d_in[3];
    const float* bk = (const float*)d_in[4];
    const float* Wv = (const float*)d_in[5];
    const float* bv = (const float*)d_in[6];
    const float* Wo = (const float*)d_in[7];
    const float* bo = (const float*)d_in[8];
    float* out = (float*)d_out;

    __nv_bfloat16 *xhi, *xlo, *w0h, *w0l, *w1h, *w1l, *w2h, *w2l, *w3h, *w3l, *ahi, *alo;
    __nv_bfloat16 *qh, *ql, *kh, *kl, *vh, *vl;
    cudaGetSymbolAddress((void**)&xhi, g_xhi);  cudaGetSymbolAddress((void**)&xlo, g_xlo);
    cudaGetSymbolAddress((void**)&w0h, g_W0hi); cudaGetSymbolAddress((void**)&w0l, g_W0lo);
    cudaGetSymbolAddress((void**)&w1h, g_W1hi); cudaGetSymbolAddress((void**)&w1l, g_W1lo);
    cudaGetSymbolAddress((void**)&w2h, g_W2hi); cudaGetSymbolAddress((void**)&w2l, g_W2lo);
    cudaGetSymbolAddress((void**)&w3h, g_W3hi); cudaGetSymbolAddress((void**)&w3l, g_W3lo);
    cudaGetSymbolAddress((void**)&ahi, g_Ahi);  cudaGetSymbolAddress((void**)&alo, g_Alo);
    cudaGetSymbolAddress((void**)&qh, g_Qhi);   cudaGetSymbolAddress((void**)&ql, g_Qlo);
    cudaGetSymbolAddress((void**)&kh, g_Khi);   cudaGetSymbolAddress((void**)&kl, g_Klo);
    cudaGetSymbolAddress((void**)&vh, g_Vhi);   cudaGetSymbolAddress((void**)&vl, g_Vlo);

    cudaFuncSetAttribute(gemm_tc2<0>, cudaFuncAttributeMaxDynamicSharedMemorySize, GEMM_DSMEM);
    cudaFuncSetAttribute(gemm_tc2<1>, cudaFuncAttributeMaxDynamicSharedMemorySize, GEMM_DSMEM);
    cudaFuncSetAttribute(flash_mma, cudaFuncAttributeMaxDynamicSharedMemorySize, FLASH_DSMEM);

    split_bf16<<<MTOT * DMODEL / 4 / 256, 256>>>(x,  xhi, xlo, MTOT * DMODEL / 4);
    split_bf16<<<DMODEL * DMODEL / 4 / 256, 256>>>(Wq, w0h, w0l, DMODEL * DMODEL / 4);
    split_bf16<<<DMODEL * DMODEL / 4 / 256, 256>>>(Wk, w1h, w1l, DMODEL * DMODEL / 4);
    split_bf16<<<DMODEL * DMODEL / 4 / 256, 256>>>(Wv, w2h, w2l, DMODEL * DMODEL / 4);
    split_bf16<<<DMODEL * DMODEL / 4 / 256, 256>>>(Wo, w3h, w3l, DMODEL * DMODEL / 4);

    dim3 ggrid(DMODEL / TN, MTOT / TM);   // (8, 32)
    // Q projection pre-scaled by 1/sqrt(HDIM) = 0.125
    gemm_tc2<1><<<ggrid, 256, GEMM_DSMEM>>>(xhi, xlo, w0h, w0l, bq, nullptr, qh, ql, 0.125f);
    gemm_tc2<1><<<ggrid, 256, GEMM_DSMEM>>>(xhi, xlo, w1h, w1l, bk, nullptr, kh, kl, 1.0f);
    gemm_tc2<1><<<ggrid, 256, GEMM_DSMEM>>>(xhi, xlo, w2h, w2l, bv, nullptr, vh, vl, 1.0f);

    dim3 agrid(NSEQ / FBR, BH);           // (16, 32)
    flash_mma<<<agrid, 256, FLASH_DSMEM>>>(qh, ql, kh, kl, vh, vl, ahi, alo);

    gemm_tc2<0><<<ggrid, 256, GEMM_DSMEM>>>(ahi, alo, w3h, w3l, bo, out, nullptr, nullptr, 1.0f);
}

// round 5
// speedup vs baseline: 2.9827x; 1.0239x over previous
#include <cuda_runtime.h>
#include <cuda_bf16.h>
#include <cstddef>
#include <cstdint>

// Problem constants
#define B_SZ   2
#define NSEQ   2048
#define DMODEL 1024
#define NHEAD  16
#define HDIM   64
#define MTOT   (B_SZ * NSEQ)      // 4096
#define BH     (B_SZ * NHEAD)     // 32

// ---------------------------------------------------------------------------
// Scratch (static device arrays; no allocation allowed)
// ---------------------------------------------------------------------------
__device__ __nv_bfloat16 g_xhi[MTOT * DMODEL];
__device__ __nv_bfloat16 g_xlo[MTOT * DMODEL];
__device__ __nv_bfloat16 g_W0hi[DMODEL * DMODEL];
__device__ __nv_bfloat16 g_W0lo[DMODEL * DMODEL];
__device__ __nv_bfloat16 g_W1hi[DMODEL * DMODEL];
__device__ __nv_bfloat16 g_W1lo[DMODEL * DMODEL];
__device__ __nv_bfloat16 g_W2hi[DMODEL * DMODEL];
__device__ __nv_bfloat16 g_W2lo[DMODEL * DMODEL];
__device__ __nv_bfloat16 g_W3hi[DMODEL * DMODEL];
__device__ __nv_bfloat16 g_W3lo[DMODEL * DMODEL];
__device__ __nv_bfloat16 g_Ahi[MTOT * DMODEL];
__device__ __nv_bfloat16 g_Alo[MTOT * DMODEL];
// QKV in bf16 hi/lo, [bh][n][64]
__device__ __nv_bfloat16 g_Qhi[BH * NSEQ * HDIM];
__device__ __nv_bfloat16 g_Qlo[BH * NSEQ * HDIM];
__device__ __nv_bfloat16 g_Khi[BH * NSEQ * HDIM];
__device__ __nv_bfloat16 g_Klo[BH * NSEQ * HDIM];
__device__ __nv_bfloat16 g_Vhi[BH * NSEQ * HDIM];
__device__ __nv_bfloat16 g_Vlo[BH * NSEQ * HDIM];

// ---------------------------------------------------------------------------
// PTX helpers (base compute_103: cp.async, ldmatrix, mma.sync)
// ---------------------------------------------------------------------------
__device__ __forceinline__ uint32_t s2u(const void* p) {
    uint32_t r;
    asm("{ .reg .u64 t; cvta.to.shared.u64 t, %1; cvt.u32.u64 %0, t; }" : "=r"(r) : "l"(p));
    return r;
}
__device__ __forceinline__ void cpa16(uint32_t dst, const void* src) {
    asm volatile("cp.async.cg.shared.global [%0], [%1], 16;" :: "r"(dst), "l"(src));
}
__device__ __forceinline__ void ldsm_x4(uint32_t* r, uint32_t addr) {
    asm volatile("ldmatrix.sync.aligned.m8n8.x4.shared.b16 {%0,%1,%2,%3}, [%4];"
                 : "=r"(r[0]), "=r"(r[1]), "=r"(r[2]), "=r"(r[3]) : "r"(addr));
}
__device__ __forceinline__ void ldsm_x4_t(uint32_t* r, uint32_t addr) {
    asm volatile("ldmatrix.sync.aligned.m8n8.x4.trans.shared.b16 {%0,%1,%2,%3}, [%4];"
                 : "=r"(r[0]), "=r"(r[1]), "=r"(r[2]), "=r"(r[3]) : "r"(addr));
}
__device__ __forceinline__ void mma16816(float* c, const uint32_t* a, const uint32_t* b) {
    asm volatile("mma.sync.aligned.m16n8k16.row.col.f32.bf16.bf16.f32 "
                 "{%0,%1,%2,%3}, {%4,%5,%6,%7}, {%8,%9}, {%0,%1,%2,%3};"
                 : "+f"(c[0]), "+f"(c[1]), "+f"(c[2]), "+f"(c[3])
                 : "r"(a[0]), "r"(a[1]), "r"(a[2]), "r"(a[3]), "r"(b[0]), "r"(b[1]));
}

// bf16 hi/lo split: returns packed hi pair, writes packed lo pair
__device__ __forceinline__ uint32_t pack2_split(float x, float y, uint32_t& lopack) {
    __nv_bfloat16 hx = __float2bfloat16(x);
    __nv_bfloat16 hy = __float2bfloat16(y);
    __nv_bfloat16 lx = __float2bfloat16(x - __bfloat162float(hx));
    __nv_bfloat16 ly = __float2bfloat16(y - __bfloat162float(hy));
    lopack = (uint32_t)__bfloat16_as_ushort(lx) | ((uint32_t)__bfloat16_as_ushort(ly) << 16);
    return (uint32_t)__bfloat16_as_ushort(hx) | ((uint32_t)__bfloat16_as_ushort(hy) << 16);
}

// ---------------------------------------------------------------------------
// fp32 -> bf16 hi/lo split precompute
// ---------------------------------------------------------------------------
__global__ void split_bf16(const float* __restrict__ in,
                           __nv_bfloat16* __restrict__ hi,
                           __nv_bfloat16* __restrict__ lo, int n4)
{
    int i = blockIdx.x * blockDim.x + threadIdx.x;
    if (i >= n4) return;
    float4 v = reinterpret_cast<const float4*>(in)[i];
    uint2 h, l;
    h.x = pack2_split(v.x, v.y, l.x);
    h.y = pack2_split(v.z, v.w, l.y);
    reinterpret_cast<uint2*>(hi)[i] = h;
    reinterpret_cast<uint2*>(lo)[i] = l;
}

// Fused split for the 4 weight matrices (grid.y selects matrix)
__global__ void split_bf16_w(const float* __restrict__ w0, const float* __restrict__ w1,
                             const float* __restrict__ w2, const float* __restrict__ w3,
                             __nv_bfloat16* __restrict__ h0, __nv_bfloat16* __restrict__ l0,
                             __nv_bfloat16* __restrict__ h1, __nv_bfloat16* __restrict__ l1,
                             __nv_bfloat16* __restrict__ h2, __nv_bfloat16* __restrict__ l2,
                             __nv_bfloat16* __restrict__ h3, __nv_bfloat16* __restrict__ l3,
                             int n4)
{
    int i = blockIdx.x * blockDim.x + threadIdx.x;
    if (i >= n4) return;
    const float* in; __nv_bfloat16 *hi, *lo;
    switch (blockIdx.y) {
        case 0: in = w0; hi = h0; lo = l0; break;
        case 1: in = w1; hi = h1; lo = l1; break;
        case 2: in = w2; hi = h2; lo = l2; break;
        default: in = w3; hi = h3; lo = l3; break;
    }
    float4 v = reinterpret_cast<const float4*>(in)[i];
    uint2 h, l;
    h.x = pack2_split(v.x, v.y, l.x);
    h.y = pack2_split(v.z, v.w, l.y);
    reinterpret_cast<uint2*>(hi)[i] = h;
    reinterpret_cast<uint2*>(lo)[i] = l;
}

// ---------------------------------------------------------------------------
// HMMA bf16-split GEMM core (4-stage cp.async pipeline, 1 sync/chunk).
// C[m,n] = (sum_k A[m,k]*W[n,k] + bias[n]) * scale
// MODE 0: fp32 C row-major.  MODE 1: bf16 hi/lo scatter to [bh][nseq][hd].
// ---------------------------------------------------------------------------
#define TM 128
#define TN 128
#define KC 32
#define CHUNKS (DMODEL / KC)       // 32
#define TILE_B  8192               // 128 rows x 64 bytes
#define STAGE_B (4 * TILE_B)       // 32 KB
#define GEMM_DSMEM (4 * STAGE_B)   // 128 KB

__device__ __forceinline__ uint32_t swz(uint32_t row, uint32_t chunk) {
    return row * 64u + ((chunk ^ ((row >> 1) & 3u)) << 4);
}

template <int MODE>
__device__ __forceinline__ void gemm_core(
        const __nv_bfloat16* __restrict__ Ahi, const __nv_bfloat16* __restrict__ Alo,
        const __nv_bfloat16* __restrict__ Bhi, const __nv_bfloat16* __restrict__ Blo,
        const float* __restrict__ bias, float* __restrict__ C,
        __nv_bfloat16* __restrict__ Chi, __nv_bfloat16* __restrict__ Clo,
        float scale, char* dsm, int m0, int n0)
{
    const uint32_t sbase = s2u(dsm);
    const int tid  = threadIdx.x;
    const int wid  = tid >> 5;
    const int lane = tid & 31;
    const int wm = (wid & 3) * 32;
    const int wn = (wid >> 2) * 64;

    float acc[2][8][4];
#pragma unroll
    for (int i = 0; i < 2; i++)
#pragma unroll
        for (int j = 0; j < 8; j++)
#pragma unroll
            for (int q = 0; q < 4; q++) acc[i][j][q] = 0.f;

    const uint32_t lrow = (uint32_t)(tid >> 1);
    const uint32_t lch  = (uint32_t)(tid & 1) * 2;

    auto load_chunk = [&](int ch, int s) {
        const uint32_t sb = sbase + (uint32_t)s * STAGE_B;
        const size_t gA = (size_t)(m0 + lrow) * DMODEL + (size_t)ch * KC + lch * 8;
        const size_t gB = (size_t)(n0 + lrow) * DMODEL + (size_t)ch * KC + lch * 8;
#pragma unroll
        for (int c = 0; c < 2; c++) {
            uint32_t so = swz(lrow, lch + c);
            cpa16(sb + 0 * TILE_B + so, Ahi + gA + c * 8);
            cpa16(sb + 1 * TILE_B + so, Alo + gA + c * 8);
            cpa16(sb + 2 * TILE_B + so, Bhi + gB + c * 8);
            cpa16(sb + 3 * TILE_B + so, Blo + gB + c * 8);
        }
        asm volatile("cp.async.commit_group;" ::: "memory");
    };

    load_chunk(0, 0);
    load_chunk(1, 1);

    for (int ch = 0; ch < CHUNKS; ++ch) {
        if (ch + 2 < CHUNKS) {
            load_chunk(ch + 2, (ch + 2) & 3);
            asm volatile("cp.async.wait_group 2;" ::: "memory");
        } else if (ch + 1 < CHUNKS) {
            asm volatile("cp.async.wait_group 1;" ::: "memory");
        } else {
            asm volatile("cp.async.wait_group 0;" ::: "memory");
        }
        __syncthreads();

        const uint32_t sb = sbase + (uint32_t)(ch & 3) * STAGE_B;
#pragma unroll
        for (int kstep = 0; kstep < 2; kstep++) {
            const uint32_t kc = (uint32_t)kstep * 2;
            uint32_t a_hi[2][4], a_lo[2][4];
#pragma unroll
            for (int mf = 0; mf < 2; mf++) {
                uint32_t row = (uint32_t)(wm + mf * 16 + (lane & 15));
                uint32_t chn = kc + (uint32_t)(lane >> 4);
                ldsm_x4(a_hi[mf], sb + 0 * TILE_B + swz(row, chn));
                ldsm_x4(a_lo[mf], sb + 1 * TILE_B + swz(row, chn));
            }
            uint32_t b_hi[8][2], b_lo[8][2];
#pragma unroll
            for (int nf2 = 0; nf2 < 4; nf2++) {
                uint32_t row = (uint32_t)(wn + nf2 * 16 + 8 * (lane >> 4) + (lane & 7));
                uint32_t chn = kc + (uint32_t)((lane >> 3) & 1);
                uint32_t t[4];
                ldsm_x4(t, sb + 2 * TILE_B + swz(row, chn));
                b_hi[2 * nf2][0] = t[0]; b_hi[2 * nf2][1] = t[1];
                b_hi[2 * nf2 + 1][0] = t[2]; b_hi[2 * nf2 + 1][1] = t[3];
                ldsm_x4(t, sb + 3 * TILE_B + swz(row, chn));
                b_lo[2 * nf2][0] = t[0]; b_lo[2 * nf2][1] = t[1];
                b_lo[2 * nf2 + 1][0] = t[2]; b_lo[2 * nf2 + 1][1] = t[3];
            }
#pragma unroll
            for (int mf = 0; mf < 2; mf++)
#pragma unroll
                for (int nf = 0; nf < 8; nf++) {
                    mma16816(acc[mf][nf], a_hi[mf], b_hi[nf]);
                    mma16816(acc[mf][nf], a_hi[mf], b_lo[nf]);
                    mma16816(acc[mf][nf], a_lo[mf], b_hi[nf]);
                }
        }
        __syncthreads();
    }

#pragma unroll
    for (int mf = 0; mf < 2; mf++) {
        const int rbase = m0 + wm + mf * 16 + (lane >> 2);
#pragma unroll
        for (int nf = 0; nf < 8; nf++) {
            const int n = n0 + wn + nf * 8 + (lane & 3) * 2;
            const float b0 = bias[n], b1 = bias[n + 1];
#pragma unroll
            for (int half = 0; half < 2; half++) {
                const int m = rbase + half * 8;
                float v0 = (acc[mf][nf][2 * half] + b0) * scale;
                float v1 = (acc[mf][nf][2 * half + 1] + b1) * scale;
                if (MODE == 0) {
                    *reinterpret_cast<float2*>(C + (size_t)m * DMODEL + n) =
                        make_float2(v0, v1);
                } else {
                    int h = n >> 6, hd = n & 63;
                    int b  = m >> 11, ns = m & 2047;
                    size_t idx = (((size_t)(b * NHEAD + h) * NSEQ) + ns) * HDIM + hd;
                    uint32_t lp, hp = pack2_split(v0, v1, lp);
                    *reinterpret_cast<uint32_t*>(Chi + idx) = hp;
                    *reinterpret_cast<uint32_t*>(Clo + idx) = lp;
                }
            }
        }
    }
}

// Fused Q/K/V projection: blockIdx.z selects weight/bias/output/scale
__global__ void __launch_bounds__(256, 1)
gemm_qkv(const __nv_bfloat16* __restrict__ xhi, const __nv_bfloat16* __restrict__ xlo,
         const __nv_bfloat16* __restrict__ w0h, const __nv_bfloat16* __restrict__ w0l,
         const __nv_bfloat16* __restrict__ w1h, const __nv_bfloat16* __restrict__ w1l,
         const __nv_bfloat16* __restrict__ w2h, const __nv_bfloat16* __restrict__ w2l,
         const float* __restrict__ bq, const float* __restrict__ bk,
         const float* __restrict__ bv,
         __nv_bfloat16* __restrict__ qh, __nv_bfloat16* __restrict__ ql,
         __nv_bfloat16* __restrict__ kh, __nv_bfloat16* __restrict__ kl,
         __nv_bfloat16* __restrict__ vh, __nv_bfloat16* __restrict__ vl)
{
    extern __shared__ char dsm[];
    const int m0 = blockIdx.y * TM;
    const int n0 = blockIdx.x * TN;
    const __nv_bfloat16 *Bh, *Bl; const float* bias;
    __nv_bfloat16 *Ch, *Cl; float scale;
    switch (blockIdx.z) {
        case 0:  Bh = w0h; Bl = w0l; bias = bq; Ch = qh; Cl = ql; scale = 0.125f; break;
        case 1:  Bh = w1h; Bl = w1l; bias = bk; Ch = kh; Cl = kl; scale = 1.0f;   break;
        default: Bh = w2h; Bl = w2l; bias = bv; Ch = vh; Cl = vl; scale = 1.0f;   break;
    }
    gemm_core<1>(xhi, xlo, Bh, Bl, bias, nullptr, Ch, Cl, scale, dsm, m0, n0);
}

// O projection (fp32 output)
__global__ void __launch_bounds__(256, 1)
gemm_out(const __nv_bfloat16* __restrict__ Ahi, const __nv_bfloat16* __restrict__ Alo,
         const __nv_bfloat16* __restrict__ Bhi, const __nv_bfloat16* __restrict__ Blo,
         const float* __restrict__ bias, float* __restrict__ C)
{
    extern __shared__ char dsm[];
    gemm_core<0>(Ahi, Alo, Bhi, Blo, bias, C, nullptr, nullptr, 1.0f, dsm,
                 blockIdx.y * TM, blockIdx.x * TN);
}

// ---------------------------------------------------------------------------
// HMMA flash attention, bf16-split, 4-stage KV pipeline (1 sync/kt).
// ---------------------------------------------------------------------------
#define FBR 128
#define FBC 64
#define FKT (NSEQ / FBC)          // 32
#define FQHI 0
#define FQLO 16384
#define FSTG0 32768
#define FSTG_B 32768
#define FLASH_DSMEM (32768 + 4 * FSTG_B)   // 160 KB

__device__ __forceinline__ uint32_t swz8(uint32_t row, uint32_t chunk) {
    return row * 128u + ((chunk ^ (row & 7u)) << 4);
}

__global__ void __launch_bounds__(256, 1)
flash_mma(const __nv_bfloat16* __restrict__ Qhi, const __nv_bfloat16* __restrict__ Qlo,
          const __nv_bfloat16* __restrict__ Khi, const __nv_bfloat16* __restrict__ Klo,
          const __nv_bfloat16* __restrict__ Vhi, const __nv_bfloat16* __restrict__ Vlo,
          __nv_bfloat16* __restrict__ Ohi, __nv_bfloat16* __restrict__ Olo)
{
    extern __shared__ char fsm[];
    const uint32_t sbase = s2u(fsm);

    const int tid  = threadIdx.x;
    const int wid  = tid >> 5;
    const int lane = tid & 31;
    const int bh   = blockIdx.y;
    const int q0   = blockIdx.x * FBR;

    const size_t hb = (size_t)bh * NSEQ * HDIM;
    const __nv_bfloat16* Qh = Qhi + hb; const __nv_bfloat16* Ql = Qlo + hb;
    const __nv_bfloat16* Kh = Khi + hb; const __nv_bfloat16* Kl = Klo + hb;
    const __nv_bfloat16* Vh = Vhi + hb; const __nv_bfloat16* Vl = Vlo + hb;

    // ---- Q tile load (once): joins the first commit group
    {
        const uint32_t row = (uint32_t)(tid >> 1);
        const uint32_t c0  = (uint32_t)(tid & 1) * 4;
        const size_t g = (size_t)(q0 + row) * HDIM + c0 * 8;
#pragma unroll
        for (int c = 0; c < 4; c++) {
            uint32_t sw = swz8(row, c0 + c);
            cpa16(sbase + FQHI + sw, Qh + g + c * 8);
            cpa16(sbase + FQLO + sw, Ql + g + c * 8);
        }
    }
    auto load_kv = [&](int kt, int s) {
        const uint32_t sb = sbase + FSTG0 + (uint32_t)s * FSTG_B;
        const uint32_t row = (uint32_t)(tid >> 2);
        const uint32_t cc  = (uint32_t)(tid & 3) * 2;
        const size_t g = (size_t)(kt * FBC + row) * HDIM + cc * 8;
#pragma unroll
        for (int j = 0; j < 2; j++) {
            uint32_t sw = swz8(row, cc + j);
            cpa16(sb +     0u + sw, Kh + g + j * 8);
            cpa16(sb +  8192u + sw, Kl + g + j * 8);
            cpa16(sb + 16384u + sw, Vh + g + j * 8);
            cpa16(sb + 24576u + sw, Vl + g + j * 8);
        }
        asm volatile("cp.async.commit_group;" ::: "memory");
    };
    load_kv(0, 0);   // group also carries Q
    load_kv(1, 1);

    float o[8][4];
#pragma unroll
    for (int j = 0; j < 8; j++)
#pragma unroll
        for (int q = 0; q < 4; q++) o[j][q] = 0.f;
    float m0s = -1e30f, m1s = -1e30f, l0s = 0.f, l1s = 0.f;
    uint32_t aQh[4][4], aQl[4][4];

    const uint32_t la15 = (uint32_t)(lane & 15);
    const uint32_t la7  = (uint32_t)(lane & 7);
    const uint32_t lb8  = 8u * (uint32_t)(lane >> 4);
    const uint32_t lbc  = (uint32_t)((lane >> 3) & 1);
    const uint32_t lac  = (uint32_t)(lane >> 4);

    for (int kt = 0; kt < FKT; kt++) {
        if (kt + 2 < FKT) {
            load_kv(kt + 2, (kt + 2) & 3);
            asm volatile("cp.async.wait_group 2;" ::: "memory");
        } else if (kt + 1 < FKT) {
            asm volatile("cp.async.wait_group 1;" ::: "memory");
        } else {
            asm volatile("cp.async.wait_group 0;" ::: "memory");
        }
        __syncthreads();

        if (kt == 0) {
#pragma unroll
            for (int kf = 0; kf < 4; kf++) {
                uint32_t ad = swz8((uint32_t)(wid * 16) + la15, 2u * kf + lac);
                ldsm_x4(aQh[kf], sbase + FQHI + ad);
                ldsm_x4(aQl[kf], sbase + FQLO + ad);
            }
        }

        const uint32_t sb = sbase + FSTG0 + (uint32_t)(kt & 3) * FSTG_B;
        float acc[8][4];
#pragma unroll
        for (int j = 0; j < 8; j++)
#pragma unroll
            for (int q = 0; q < 4; q++) acc[j][q] = 0.f;

        // ---- S = Q K^T
#pragma unroll
        for (int kf = 0; kf < 4; kf++) {
#pragma unroll
            for (int np = 0; np < 4; np++) {
                uint32_t ad = swz8((uint32_t)(np * 16) + la7 + lb8, 2u * kf + lbc);
                uint32_t kh[4], kl[4];
                ldsm_x4(kh, sb + 0u + ad);
                ldsm_x4(kl, sb + 8192u + ad);
                uint32_t b0h[2] = {kh[0], kh[1]}, b1h[2] = {kh[2], kh[3]};
                uint32_t b0l[2] = {kl[0], kl[1]}, b1l[2] = {kl[2], kl[3]};
                mma16816(acc[2 * np],     aQh[kf], b0h);
                mma16816(acc[2 * np + 1], aQh[kf], b1h);
                mma16816(acc[2 * np],     aQh[kf], b0l);
                mma16816(acc[2 * np + 1], aQh[kf], b1l);
                mma16816(acc[2 * np],     aQl[kf], b0h);
                mma16816(acc[2 * np + 1], aQl[kf], b1h);
            }
        }

        // ---- online softmax
        float mx0 = -1e30f, mx1 = -1e30f;
#pragma unroll
        for (int nf = 0; nf < 8; nf++) {
            mx0 = fmaxf(mx0, fmaxf(acc[nf][0], acc[nf][1]));
            mx1 = fmaxf(mx1, fmaxf(acc[nf][2], acc[nf][3]));
        }
        mx0 = fmaxf(mx0, __shfl_xor_sync(0xffffffffu, mx0, 1));
        mx0 = fmaxf(mx0, __shfl_xor_sync(0xffffffffu, mx0, 2));
        mx1 = fmaxf(mx1, __shfl_xor_sync(0xffffffffu, mx1, 1));
        mx1 = fmaxf(mx1, __shfl_xor_sync(0xffffffffu, mx1, 2));
        float mn0 = fmaxf(m0s, mx0), mn1 = fmaxf(m1s, mx1);
        float al0 = __expf(m0s - mn0), al1 = __expf(m1s - mn1);
        m0s = mn0; m1s = mn1;
        float sum0 = 0.f, sum1 = 0.f;
#pragma unroll
        for (int nf = 0; nf < 8; nf++) {
            acc[nf][0] = __expf(acc[nf][0] - mn0);
            acc[nf][1] = __expf(acc[nf][1] - mn0);
            acc[nf][2] = __expf(acc[nf][2] - mn1);
            acc[nf][3] = __expf(acc[nf][3] - mn1);
            sum0 += acc[nf][0] + acc[nf][1];
            sum1 += acc[nf][2] + acc[nf][3];
        }
        sum0 += __shfl_xor_sync(0xffffffffu, sum0, 1);
        sum0 += __shfl_xor_sync(0xffffffffu, sum0, 2);
        sum1 += __shfl_xor_sync(0xffffffffu, sum1, 1);
        sum1 += __shfl_xor_sync(0xffffffffu, sum1, 2);
        l0s = l0s * al0 + sum0;
        l1s = l1s * al1 + sum1;
#pragma unroll
        for (int nf = 0; nf < 8; nf++) {
            o[nf][0] *= al0; o[nf][1] *= al0;
            o[nf][2] *= al1; o[nf][3] *= al1;
        }
        uint32_t pH[4][4], pL[4][4];
#pragma unroll
        for (int kf = 0; kf < 4; kf++) {
            pH[kf][0] = pack2_split(acc[2 * kf][0],     acc[2 * kf][1],     pL[kf][0]);
            pH[kf][1] = pack2_split(acc[2 * kf][2],     acc[2 * kf][3],     pL[kf][1]);
            pH[kf][2] = pack2_split(acc[2 * kf + 1][0], acc[2 * kf + 1][1], pL[kf][2]);
            pH[kf][3] = pack2_split(acc[2 * kf + 1][2], acc[2 * kf + 1][3], pL[kf][3]);
        }

        // ---- O += P V
#pragma unroll
        for (int kf = 0; kf < 4; kf++) {
#pragma unroll
            for (int dp = 0; dp < 4; dp++) {
                uint32_t ad = swz8((uint32_t)(kf * 16) + la15, 2u * dp + lac);
                uint32_t vh[4], vl[4];
                ldsm_x4_t(vh, sb + 16384u + ad);
                ldsm_x4_t(vl, sb + 24576u + ad);
                uint32_t bh0[2] = {vh[0], vh[1]}, bh1[2] = {vh[2], vh[3]};
                uint32_t bl0[2] = {vl[0], vl[1]}, bl1[2] = {vl[2], vl[3]};
                mma16816(o[2 * dp],     pH[kf], bh0);
                mma16816(o[2 * dp + 1], pH[kf], bh1);
                mma16816(o[2 * dp],     pH[kf], bl0);
                mma16816(o[2 * dp + 1], pH[kf], bl1);
                mma16816(o[2 * dp],     pL[kf], bh0);
                mma16816(o[2 * dp + 1], pL[kf], bh1);
            }
        }
    }

    // ---- normalize + write bf16 hi/lo to [B,N,D]
    const int bb = bh >> 4;
    const int h  = bh & 15;
    const float inv0 = 1.f / l0s, inv1 = 1.f / l1s;
    const int qlo = q0 + wid * 16 + (lane >> 2);
#pragma unroll
    for (int nf = 0; nf < 8; nf++) {
        const int gcol = h * HDIM + nf * 8 + (lane & 3) * 2;
        uint32_t lp, hp;
        hp = pack2_split(o[nf][0] * inv0, o[nf][1] * inv0, lp);
        size_t i0 = ((size_t)(bb * NSEQ + qlo)) * DMODEL + gcol;
        *reinterpret_cast<uint32_t*>(Ohi + i0) = hp;
        *reinterpret_cast<uint32_t*>(Olo + i0) = lp;
        hp = pack2_split(o[nf][2] * inv1, o[nf][3] * inv1, lp);
        size_t i1 = ((size_t)(bb * NSEQ + qlo + 8)) * DMODEL + gcol;
        *reinterpret_cast<uint32_t*>(Ohi + i1) = hp;
        *reinterpret_cast<uint32_t*>(Olo + i1) = lp;
    }
}

// ---------------------------------------------------------------------------
// Launch
// ---------------------------------------------------------------------------
extern "C" void kernel_launch(void* const* d_in, const int* in_sizes, int n_in,
                              void* d_out, int out_size)
{
    const float* x  = (const float*)d_in[0];
    const float* Wq = (const float*)d_in[1];
    const float* bq = (const float*)d_in[2];
    const float* Wk = (const float*)d_in[3];
    const float* bk = (const float*)d_in[4];
    const float* Wv = (const float*)d_in[5];
    const float* bv = (const float*)d_in[6];
    const float* Wo = (const float*)d_in[7];
    const float* bo = (const float*)d_in[8];
    float* out = (float*)d_out;

    __nv_bfloat16 *xhi, *xlo, *w0h, *w0l, *w1h, *w1l, *w2h, *w2l, *w3h, *w3l, *ahi, *alo;
    __nv_bfloat16 *qh, *ql, *kh, *kl, *vh, *vl;
    cudaGetSymbolAddress((void**)&xhi, g_xhi);  cudaGetSymbolAddress((void**)&xlo, g_xlo);
    cudaGetSymbolAddress((void**)&w0h, g_W0hi); cudaGetSymbolAddress((void**)&w0l, g_W0lo);
    cudaGetSymbolAddress((void**)&w1h, g_W1hi); cudaGetSymbolAddress((void**)&w1l, g_W1lo);
    cudaGetSymbolAddress((void**)&w2h, g_W2hi); cudaGetSymbolAddress((void**)&w2l, g_W2lo);
    cudaGetSymbolAddress((void**)&w3h, g_W3hi); cudaGetSymbolAddress((void**)&w3l, g_W3lo);
    cudaGetSymbolAddress((void**)&ahi, g_Ahi);  cudaGetSymbolAddress((void**)&alo, g_Alo);
    cudaGetSymbolAddress((void**)&qh, g_Qhi);   cudaGetSymbolAddress((void**)&ql, g_Qlo);
    cudaGetSymbolAddress((void**)&kh, g_Khi);   cudaGetSymbolAddress((void**)&kl, g_Klo);
    cudaGetSymbolAddress((void**)&vh, g_Vhi);   cudaGetSymbolAddress((void**)&vl, g_Vlo);

    cudaFuncSetAttribute(gemm_qkv, cudaFuncAttributeMaxDynamicSharedMemorySize, GEMM_DSMEM);
    cudaFuncSetAttribute(gemm_out, cudaFuncAttributeMaxDynamicSharedMemorySize, GEMM_DSMEM);
    cudaFuncSetAttribute(flash_mma, cudaFuncAttributeMaxDynamicSharedMemorySize, FLASH_DSMEM);

    // Splits: x (1 launch) + 4 weights (1 launch)
    split_bf16<<<MTOT * DMODEL / 4 / 256, 256>>>(x, xhi, xlo, MTOT * DMODEL / 4);
    dim3 wgrid(DMODEL * DMODEL / 4 / 256, 4);
    split_bf16_w<<<wgrid, 256>>>(Wq, Wk, Wv, Wo,
                                 w0h, w0l, w1h, w1l, w2h, w2l, w3h, w3l,
                                 DMODEL * DMODEL / 4);

    // Fused QKV projections (z selects matrix); Q pre-scaled by 0.125
    dim3 qgrid(DMODEL / TN, MTOT / TM, 3);   // (8, 32, 3)
    gemm_qkv<<<qgrid, 256, GEMM_DSMEM>>>(xhi, xlo, w0h, w0l, w1h, w1l, w2h, w2l,
                                         bq, bk, bv, qh, ql, kh, kl, vh, vl);

    dim3 agrid(NSEQ / FBR, BH);              // (16, 32)
    flash_mma<<<agrid, 256, FLASH_DSMEM>>>(qh, ql, kh, kl, vh, vl, ahi, alo);

    dim3 ogrid(DMODEL / TN, MTOT / TM);      // (8, 32)
    gemm_out<<<ogrid, 256, GEMM_DSMEM>>>(ahi, alo, w3h, w3l, bo, out);
}

// round 6
// speedup vs baseline: 3.2530x; 1.0906x over previous
#include <cuda_runtime.h>
#include <cuda_bf16.h>
#include <cstddef>
#include <cstdint>

// Problem constants
#define B_SZ   2
#define NSEQ   2048
#define DMODEL 1024
#define NHEAD  16
#define HDIM   64
#define MTOT   (B_SZ * NSEQ)      // 4096
#define BH     (B_SZ * NHEAD)     // 32

// ---------------------------------------------------------------------------
// Scratch (static device arrays; no allocation allowed)
// ---------------------------------------------------------------------------
__device__ __nv_bfloat16 g_xhi[MTOT * DMODEL];
__device__ __nv_bfloat16 g_xlo[MTOT * DMODEL];
__device__ __nv_bfloat16 g_W0hi[DMODEL * DMODEL];
__device__ __nv_bfloat16 g_W0lo[DMODEL * DMODEL];
__device__ __nv_bfloat16 g_W1hi[DMODEL * DMODEL];
__device__ __nv_bfloat16 g_W1lo[DMODEL * DMODEL];
__device__ __nv_bfloat16 g_W2hi[DMODEL * DMODEL];
__device__ __nv_bfloat16 g_W2lo[DMODEL * DMODEL];
__device__ __nv_bfloat16 g_W3hi[DMODEL * DMODEL];
__device__ __nv_bfloat16 g_W3lo[DMODEL * DMODEL];
__device__ __nv_bfloat16 g_Ahi[MTOT * DMODEL];
__device__ __nv_bfloat16 g_Alo[MTOT * DMODEL];
__device__ __nv_bfloat16 g_Qhi[BH * NSEQ * HDIM];
__device__ __nv_bfloat16 g_Qlo[BH * NSEQ * HDIM];
__device__ __nv_bfloat16 g_Khi[BH * NSEQ * HDIM];
__device__ __nv_bfloat16 g_Klo[BH * NSEQ * HDIM];
__device__ __nv_bfloat16 g_Vhi[BH * NSEQ * HDIM];
__device__ __nv_bfloat16 g_Vlo[BH * NSEQ * HDIM];

// ---------------------------------------------------------------------------
// PTX helpers
// ---------------------------------------------------------------------------
__device__ __forceinline__ uint32_t s2u(const void* p) {
    uint32_t r;
    asm("{ .reg .u64 t; cvta.to.shared.u64 t, %1; cvt.u32.u64 %0, t; }" : "=r"(r) : "l"(p));
    return r;
}
__device__ __forceinline__ void cpa16(uint32_t dst, const void* src) {
    asm volatile("cp.async.cg.shared.global [%0], [%1], 16;" :: "r"(dst), "l"(src));
}
__device__ __forceinline__ void ldsm_x4(uint32_t* r, uint32_t addr) {
    asm volatile("ldmatrix.sync.aligned.m8n8.x4.shared.b16 {%0,%1,%2,%3}, [%4];"
                 : "=r"(r[0]), "=r"(r[1]), "=r"(r[2]), "=r"(r[3]) : "r"(addr));
}
__device__ __forceinline__ void ldsm_x4_t(uint32_t* r, uint32_t addr) {
    asm volatile("ldmatrix.sync.aligned.m8n8.x4.trans.shared.b16 {%0,%1,%2,%3}, [%4];"
                 : "=r"(r[0]), "=r"(r[1]), "=r"(r[2]), "=r"(r[3]) : "r"(addr));
}
__device__ __forceinline__ void mma16816(float* c, const uint32_t* a, const uint32_t* b) {
    asm volatile("mma.sync.aligned.m16n8k16.row.col.f32.bf16.bf16.f32 "
                 "{%0,%1,%2,%3}, {%4,%5,%6,%7}, {%8,%9}, {%0,%1,%2,%3};"
                 : "+f"(c[0]), "+f"(c[1]), "+f"(c[2]), "+f"(c[3])
                 : "r"(a[0]), "r"(a[1]), "r"(a[2]), "r"(a[3]), "r"(b[0]), "r"(b[1]));
}
__device__ __forceinline__ uint32_t pack2_split(float x, float y, uint32_t& lopack) {
    __nv_bfloat16 hx = __float2bfloat16(x);
    __nv_bfloat16 hy = __float2bfloat16(y);
    __nv_bfloat16 lx = __float2bfloat16(x - __bfloat162float(hx));
    __nv_bfloat16 ly = __float2bfloat16(y - __bfloat162float(hy));
    lopack = (uint32_t)__bfloat16_as_ushort(lx) | ((uint32_t)__bfloat16_as_ushort(ly) << 16);
    return (uint32_t)__bfloat16_as_ushort(hx) | ((uint32_t)__bfloat16_as_ushort(hy) << 16);
}

// ---------------------------------------------------------------------------
// fp32 -> bf16 hi/lo splits
// ---------------------------------------------------------------------------
__global__ void split_bf16(const float* __restrict__ in,
                           __nv_bfloat16* __restrict__ hi,
                           __nv_bfloat16* __restrict__ lo, int n4)
{
    int i = blockIdx.x * blockDim.x + threadIdx.x;
    if (i >= n4) return;
    float4 v = reinterpret_cast<const float4*>(in)[i];
    uint2 h, l;
    h.x = pack2_split(v.x, v.y, l.x);
    h.y = pack2_split(v.z, v.w, l.y);
    reinterpret_cast<uint2*>(hi)[i] = h;
    reinterpret_cast<uint2*>(lo)[i] = l;
}

__global__ void split_bf16_w(const float* __restrict__ w0, const float* __restrict__ w1,
                             const float* __restrict__ w2, const float* __restrict__ w3,
                             __nv_bfloat16* __restrict__ h0, __nv_bfloat16* __restrict__ l0,
                             __nv_bfloat16* __restrict__ h1, __nv_bfloat16* __restrict__ l1,
                             __nv_bfloat16* __restrict__ h2, __nv_bfloat16* __restrict__ l2,
                             __nv_bfloat16* __restrict__ h3, __nv_bfloat16* __restrict__ l3,
                             int n4)
{
    int i = blockIdx.x * blockDim.x + threadIdx.x;
    if (i >= n4) return;
    const float* in; __nv_bfloat16 *hi, *lo;
    switch (blockIdx.y) {
        case 0: in = w0; hi = h0; lo = l0; break;
        case 1: in = w1; hi = h1; lo = l1; break;
        case 2: in = w2; hi = h2; lo = l2; break;
        default: in = w3; hi = h3; lo = l3; break;
    }
    float4 v = reinterpret_cast<const float4*>(in)[i];
    uint2 h, l;
    h.x = pack2_split(v.x, v.y, l.x);
    h.y = pack2_split(v.z, v.w, l.y);
    reinterpret_cast<uint2*>(hi)[i] = h;
    reinterpret_cast<uint2*>(lo)[i] = l;
}

// ---------------------------------------------------------------------------
// HMMA bf16-split GEMM core: 3-stage cp.async pipeline, sync-then-prefetch,
// B fragments loaded inside the MMA loop (low register pressure).
// ---------------------------------------------------------------------------
#define TM 128
#define TN 128
#define KC 32
#define CHUNKS (DMODEL / KC)       // 32
#define TILE_B  8192               // 128 rows x 64 bytes
#define STAGE_B (4 * TILE_B)       // 32 KB
#define GSTAGES 3
#define GEMM_DSMEM (GSTAGES * STAGE_B)   // 96 KB

__device__ __forceinline__ uint32_t swz(uint32_t row, uint32_t chunk) {
    return row * 64u + ((chunk ^ ((row >> 1) & 3u)) << 4);
}

template <int MODE>
__device__ __forceinline__ void gemm_core(
        const __nv_bfloat16* __restrict__ Ahi, const __nv_bfloat16* __restrict__ Alo,
        const __nv_bfloat16* __restrict__ Bhi, const __nv_bfloat16* __restrict__ Blo,
        const float* __restrict__ bias, float* __restrict__ C,
        __nv_bfloat16* __restrict__ Chi, __nv_bfloat16* __restrict__ Clo,
        float scale, char* dsm, int m0, int n0)
{
    const uint32_t sbase = s2u(dsm);
    const int tid  = threadIdx.x;
    const int wid  = tid >> 5;
    const int lane = tid & 31;
    const int wm = (wid & 3) * 32;
    const int wn = (wid >> 2) * 64;

    float acc[2][8][4];
#pragma unroll
    for (int i = 0; i < 2; i++)
#pragma unroll
        for (int j = 0; j < 8; j++)
#pragma unroll
            for (int q = 0; q < 4; q++) acc[i][j][q] = 0.f;

    const uint32_t lrow = (uint32_t)(tid >> 1);
    const uint32_t lch  = (uint32_t)(tid & 1) * 2;

    auto load_chunk = [&](int ch, int s) {
        const uint32_t sb = sbase + (uint32_t)s * STAGE_B;
        const size_t gA = (size_t)(m0 + lrow) * DMODEL + (size_t)ch * KC + lch * 8;
        const size_t gB = (size_t)(n0 + lrow) * DMODEL + (size_t)ch * KC + lch * 8;
#pragma unroll
        for (int c = 0; c < 2; c++) {
            uint32_t so = swz(lrow, lch + c);
            cpa16(sb + 0 * TILE_B + so, Ahi + gA + c * 8);
            cpa16(sb + 1 * TILE_B + so, Alo + gA + c * 8);
            cpa16(sb + 2 * TILE_B + so, Bhi + gB + c * 8);
            cpa16(sb + 3 * TILE_B + so, Blo + gB + c * 8);
        }
        asm volatile("cp.async.commit_group;" ::: "memory");
    };

    load_chunk(0, 0);
    load_chunk(1, 1);

    int stage = 0;
    for (int ch = 0; ch < CHUNKS; ++ch) {
        if (ch + 1 < CHUNKS) { asm volatile("cp.async.wait_group 1;" ::: "memory"); }
        else                 { asm volatile("cp.async.wait_group 0;" ::: "memory"); }
        __syncthreads();
        if (ch + 2 < CHUNKS) {
            int ps = stage + 2; if (ps >= GSTAGES) ps -= GSTAGES;
            load_chunk(ch + 2, ps);
        }

        const uint32_t sb = sbase + (uint32_t)stage * STAGE_B;
#pragma unroll
        for (int kstep = 0; kstep < 2; kstep++) {
            const uint32_t kc = (uint32_t)kstep * 2;
            uint32_t a_hi[2][4], a_lo[2][4];
#pragma unroll
            for (int mf = 0; mf < 2; mf++) {
                uint32_t row = (uint32_t)(wm + mf * 16 + (lane & 15));
                uint32_t chn = kc + (uint32_t)(lane >> 4);
                ldsm_x4(a_hi[mf], sb + 0 * TILE_B + swz(row, chn));
                ldsm_x4(a_lo[mf], sb + 1 * TILE_B + swz(row, chn));
            }
#pragma unroll
            for (int nf2 = 0; nf2 < 4; nf2++) {
                uint32_t row = (uint32_t)(wn + nf2 * 16 + 8 * (lane >> 4) + (lane & 7));
                uint32_t chn = kc + (uint32_t)((lane >> 3) & 1);
                uint32_t th[4], tl[4];
                ldsm_x4(th, sb + 2 * TILE_B + swz(row, chn));
                ldsm_x4(tl, sb + 3 * TILE_B + swz(row, chn));
#pragma unroll
                for (int mf = 0; mf < 2; mf++) {
                    mma16816(acc[mf][2 * nf2],     a_hi[mf], th);
                    mma16816(acc[mf][2 * nf2 + 1], a_hi[mf], th + 2);
                    mma16816(acc[mf][2 * nf2],     a_hi[mf], tl);
                    mma16816(acc[mf][2 * nf2 + 1], a_hi[mf], tl + 2);
                    mma16816(acc[mf][2 * nf2],     a_lo[mf], th);
                    mma16816(acc[mf][2 * nf2 + 1], a_lo[mf], th + 2);
                }
            }
        }
        if (++stage >= GSTAGES) stage = 0;
    }
    __syncthreads();

#pragma unroll
    for (int mf = 0; mf < 2; mf++) {
        const int rbase = m0 + wm + mf * 16 + (lane >> 2);
#pragma unroll
        for (int nf = 0; nf < 8; nf++) {
            const int n = n0 + wn + nf * 8 + (lane & 3) * 2;
            const float b0 = bias[n], b1 = bias[n + 1];
#pragma unroll
            for (int half = 0; half < 2; half++) {
                const int m = rbase + half * 8;
                float v0 = (acc[mf][nf][2 * half] + b0) * scale;
                float v1 = (acc[mf][nf][2 * half + 1] + b1) * scale;
                if (MODE == 0) {
                    *reinterpret_cast<float2*>(C + (size_t)m * DMODEL + n) =
                        make_float2(v0, v1);
                } else {
                    int h = n >> 6, hd = n & 63;
                    int b  = m >> 11, ns = m & 2047;
                    size_t idx = (((size_t)(b * NHEAD + h) * NSEQ) + ns) * HDIM + hd;
                    uint32_t lp, hp = pack2_split(v0, v1, lp);
                    *reinterpret_cast<uint32_t*>(Chi + idx) = hp;
                    *reinterpret_cast<uint32_t*>(Clo + idx) = lp;
                }
            }
        }
    }
}

// Q pre-scale folds 1/sqrt(HDIM) AND log2(e) so flash can use exp2 directly
#define QSCALE 0.18033688011112042f

__global__ void __launch_bounds__(256, 2)
gemm_qkv(const __nv_bfloat16* __restrict__ xhi, const __nv_bfloat16* __restrict__ xlo,
         const __nv_bfloat16* __restrict__ w0h, const __nv_bfloat16* __restrict__ w0l,
         const __nv_bfloat16* __restrict__ w1h, const __nv_bfloat16* __restrict__ w1l,
         const __nv_bfloat16* __restrict__ w2h, const __nv_bfloat16* __restrict__ w2l,
         const float* __restrict__ bq, const float* __restrict__ bk,
         const float* __restrict__ bv,
         __nv_bfloat16* __restrict__ qh, __nv_bfloat16* __restrict__ ql,
         __nv_bfloat16* __restrict__ kh, __nv_bfloat16* __restrict__ kl,
         __nv_bfloat16* __restrict__ vh, __nv_bfloat16* __restrict__ vl)
{
    extern __shared__ char dsm[];
    const int m0 = blockIdx.y * TM;
    const int n0 = blockIdx.x * TN;
    const __nv_bfloat16 *Bh, *Bl; const float* bias;
    __nv_bfloat16 *Ch, *Cl; float scale;
    switch (blockIdx.z) {
        case 0:  Bh = w0h; Bl = w0l; bias = bq; Ch = qh; Cl = ql; scale = QSCALE; break;
        case 1:  Bh = w1h; Bl = w1l; bias = bk; Ch = kh; Cl = kl; scale = 1.0f;   break;
        default: Bh = w2h; Bl = w2l; bias = bv; Ch = vh; Cl = vl; scale = 1.0f;   break;
    }
    gemm_core<1>(xhi, xlo, Bh, Bl, bias, nullptr, Ch, Cl, scale, dsm, m0, n0);
}

__global__ void __launch_bounds__(256, 2)
gemm_out(const __nv_bfloat16* __restrict__ Ahi, const __nv_bfloat16* __restrict__ Alo,
         const __nv_bfloat16* __restrict__ Bhi, const __nv_bfloat16* __restrict__ Blo,
         const float* __restrict__ bias, float* __restrict__ C)
{
    extern __shared__ char dsm[];
    gemm_core<0>(Ahi, Alo, Bhi, Blo, bias, C, nullptr, nullptr, 1.0f, dsm,
                 blockIdx.y * TM, blockIdx.x * TN);
}

// ---------------------------------------------------------------------------
// HMMA flash attention, bf16-split, 2-stage KV pipeline, 2 CTAs/SM.
// Q fragments reloaded from smem per kf; P packing interleaved with PV.
// ---------------------------------------------------------------------------
#define FBR 128
#define FBC 64
#define FKT (NSEQ / FBC)          // 32
#define FQHI 0
#define FQLO 16384
#define FSTG0 32768
#define FSTG_B 32768
#define FLASH_DSMEM (32768 + 2 * FSTG_B)   // 96 KB

__device__ __forceinline__ uint32_t swz8(uint32_t row, uint32_t chunk) {
    return row * 128u + ((chunk ^ (row & 7u)) << 4);
}

__global__ void __launch_bounds__(256, 2)
flash_mma(const __nv_bfloat16* __restrict__ Qhi, const __nv_bfloat16* __restrict__ Qlo,
          const __nv_bfloat16* __restrict__ Khi, const __nv_bfloat16* __restrict__ Klo,
          const __nv_bfloat16* __restrict__ Vhi, const __nv_bfloat16* __restrict__ Vlo,
          __nv_bfloat16* __restrict__ Ohi, __nv_bfloat16* __restrict__ Olo)
{
    extern __shared__ char fsm[];
    const uint32_t sbase = s2u(fsm);

    const int tid  = threadIdx.x;
    const int wid  = tid >> 5;
    const int lane = tid & 31;
    const int bh   = blockIdx.y;
    const int q0   = blockIdx.x * FBR;

    const size_t hb = (size_t)bh * NSEQ * HDIM;
    const __nv_bfloat16* Qh = Qhi + hb; const __nv_bfloat16* Ql = Qlo + hb;
    const __nv_bfloat16* Kh = Khi + hb; const __nv_bfloat16* Kl = Klo + hb;
    const __nv_bfloat16* Vh = Vhi + hb; const __nv_bfloat16* Vl = Vlo + hb;

    // Q tile load (joins first KV commit group)
    {
        const uint32_t row = (uint32_t)(tid >> 1);
        const uint32_t c0  = (uint32_t)(tid & 1) * 4;
        const size_t g = (size_t)(q0 + row) * HDIM + c0 * 8;
#pragma unroll
        for (int c = 0; c < 4; c++) {
            uint32_t sw = swz8(row, c0 + c);
            cpa16(sbase + FQHI + sw, Qh + g + c * 8);
            cpa16(sbase + FQLO + sw, Ql + g + c * 8);
        }
    }
    auto load_kv = [&](int kt, int s) {
        const uint32_t sb = sbase + FSTG0 + (uint32_t)s * FSTG_B;
        const uint32_t row = (uint32_t)(tid >> 2);
        const uint32_t cc  = (uint32_t)(tid & 3) * 2;
        const size_t g = (size_t)(kt * FBC + row) * HDIM + cc * 8;
#pragma unroll
        for (int j = 0; j < 2; j++) {
            uint32_t sw = swz8(row, cc + j);
            cpa16(sb +     0u + sw, Kh + g + j * 8);
            cpa16(sb +  8192u + sw, Kl + g + j * 8);
            cpa16(sb + 16384u + sw, Vh + g + j * 8);
            cpa16(sb + 24576u + sw, Vl + g + j * 8);
        }
        asm volatile("cp.async.commit_group;" ::: "memory");
    };
    load_kv(0, 0);

    float o[8][4];
#pragma unroll
    for (int j = 0; j < 8; j++)
#pragma unroll
        for (int q = 0; q < 4; q++) o[j][q] = 0.f;
    float m0s = -1e30f, m1s = -1e30f, l0s = 0.f, l1s = 0.f;

    const uint32_t la15 = (uint32_t)(lane & 15);
    const uint32_t la7  = (uint32_t)(lane & 7);
    const uint32_t lb8  = 8u * (uint32_t)(lane >> 4);
    const uint32_t lbc  = (uint32_t)((lane >> 3) & 1);
    const uint32_t lac  = (uint32_t)(lane >> 4);

    for (int kt = 0; kt < FKT; kt++) {
        // wait for group kt (only one in flight at loop top), sync, THEN prefetch
        asm volatile("cp.async.wait_group 0;" ::: "memory");
        __syncthreads();
        if (kt + 1 < FKT) load_kv(kt + 1, (kt + 1) & 1);

        const uint32_t sb = sbase + FSTG0 + (uint32_t)(kt & 1) * FSTG_B;
        float acc[8][4];
#pragma unroll
        for (int j = 0; j < 8; j++)
#pragma unroll
            for (int q = 0; q < 4; q++) acc[j][q] = 0.f;

        // ---- S = Q K^T (Q frags reloaded per kf: low register pressure)
#pragma unroll
        for (int kf = 0; kf < 4; kf++) {
            uint32_t aQh[4], aQl[4];
            uint32_t qad = swz8((uint32_t)(wid * 16) + la15, 2u * kf + lac);
            ldsm_x4(aQh, sbase + FQHI + qad);
            ldsm_x4(aQl, sbase + FQLO + qad);
#pragma unroll
            for (int np = 0; np < 4; np++) {
                uint32_t ad = swz8((uint32_t)(np * 16) + la7 + lb8, 2u * kf + lbc);
                uint32_t kh[4], kl[4];
                ldsm_x4(kh, sb + 0u + ad);
                ldsm_x4(kl, sb + 8192u + ad);
                mma16816(acc[2 * np],     aQh, kh);
                mma16816(acc[2 * np + 1], aQh, kh + 2);
                mma16816(acc[2 * np],     aQh, kl);
                mma16816(acc[2 * np + 1], aQh, kl + 2);
                mma16816(acc[2 * np],     aQl, kh);
                mma16816(acc[2 * np + 1], aQl, kh + 2);
            }
        }

        // ---- online softmax (base-2 domain; Q was pre-scaled by log2e/8)
        float mx0 = -1e30f, mx1 = -1e30f;
#pragma unroll
        for (int nf = 0; nf < 8; nf++) {
            mx0 = fmaxf(mx0, fmaxf(acc[nf][0], acc[nf][1]));
            mx1 = fmaxf(mx1, fmaxf(acc[nf][2], acc[nf][3]));
        }
        mx0 = fmaxf(mx0, __shfl_xor_sync(0xffffffffu, mx0, 1));
        mx0 = fmaxf(mx0, __shfl_xor_sync(0xffffffffu, mx0, 2));
        mx1 = fmaxf(mx1, __shfl_xor_sync(0xffffffffu, mx1, 1));
        mx1 = fmaxf(mx1, __shfl_xor_sync(0xffffffffu, mx1, 2));
        float mn0 = fmaxf(m0s, mx0), mn1 = fmaxf(m1s, mx1);
        float al0 = exp2f(m0s - mn0), al1 = exp2f(m1s - mn1);
        m0s = mn0; m1s = mn1;
        float sum0 = 0.f, sum1 = 0.f;
#pragma unroll
        for (int nf = 0; nf < 8; nf++) {
            acc[nf][0] = exp2f(acc[nf][0] - mn0);
            acc[nf][1] = exp2f(acc[nf][1] - mn0);
            acc[nf][2] = exp2f(acc[nf][2] - mn1);
            acc[nf][3] = exp2f(acc[nf][3] - mn1);
            sum0 += acc[nf][0] + acc[nf][1];
            sum1 += acc[nf][2] + acc[nf][3];
        }
        sum0 += __shfl_xor_sync(0xffffffffu, sum0, 1);
        sum0 += __shfl_xor_sync(0xffffffffu, sum0, 2);
        sum1 += __shfl_xor_sync(0xffffffffu, sum1, 1);
        sum1 += __shfl_xor_sync(0xffffffffu, sum1, 2);
        l0s = l0s * al0 + sum0;
        l1s = l1s * al1 + sum1;
#pragma unroll
        for (int nf = 0; nf < 8; nf++) {
            o[nf][0] *= al0; o[nf][1] *= al0;
            o[nf][2] *= al1; o[nf][3] *= al1;
        }

        // ---- O += P V : pack P per kf, consume immediately (low reg pressure)
#pragma unroll
        for (int kf = 0; kf < 4; kf++) {
            uint32_t pH[4], pL[4];
            pH[0] = pack2_split(acc[2 * kf][0],     acc[2 * kf][1],     pL[0]);
            pH[1] = pack2_split(acc[2 * kf][2],     acc[2 * kf][3],     pL[1]);
            pH[2] = pack2_split(acc[2 * kf + 1][0], acc[2 * kf + 1][1], pL[2]);
            pH[3] = pack2_split(acc[2 * kf + 1][2], acc[2 * kf + 1][3], pL[3]);
#pragma unroll
            for (int dp = 0; dp < 4; dp++) {
                uint32_t ad = swz8((uint32_t)(kf * 16) + la15, 2u * dp + lac);
                uint32_t vh[4], vl[4];
                ldsm_x4_t(vh, sb + 16384u + ad);
                ldsm_x4_t(vl, sb + 24576u + ad);
                mma16816(o[2 * dp],     pH, vh);
                mma16816(o[2 * dp + 1], pH, vh + 2);
                mma16816(o[2 * dp],     pH, vl);
                mma16816(o[2 * dp + 1], pH, vl + 2);
                mma16816(o[2 * dp],     pL, vh);
                mma16816(o[2 * dp + 1], pL, vh + 2);
            }
        }
    }

    // ---- normalize + write bf16 hi/lo to [B,N,D]
    const int bb = bh >> 4;
    const int h  = bh & 15;
    const float inv0 = 1.f / l0s, inv1 = 1.f / l1s;
    const int qlo = q0 + wid * 16 + (lane >> 2);
#pragma unroll
    for (int nf = 0; nf < 8; nf++) {
        const int gcol = h * HDIM + nf * 8 + (lane & 3) * 2;
        uint32_t lp, hp;
        hp = pack2_split(o[nf][0] * inv0, o[nf][1] * inv0, lp);
        size_t i0 = ((size_t)(bb * NSEQ + qlo)) * DMODEL + gcol;
        *reinterpret_cast<uint32_t*>(Ohi + i0) = hp;
        *reinterpret_cast<uint32_t*>(Olo + i0) = lp;
        hp = pack2_split(o[nf][2] * inv1, o[nf][3] * inv1, lp);
        size_t i1 = ((size_t)(bb * NSEQ + qlo + 8)) * DMODEL + gcol;
        *reinterpret_cast<uint32_t*>(Ohi + i1) = hp;
        *reinterpret_cast<uint32_t*>(Olo + i1) = lp;
    }
}

// ---------------------------------------------------------------------------
// Launch
// ---------------------------------------------------------------------------
extern "C" void kernel_launch(void* const* d_in, const int* in_sizes, int n_in,
                              void* d_out, int out_size)
{
    const float* x  = (const float*)d_in[0];
    const float* Wq = (const float*)d_in[1];
    const float* bq = (const float*)d_in[2];
    const float* Wk = (const float*)d_in[3];
    const float* bk = (const float*)d_in[4];
    const float* Wv = (const float*)d_in[5];
    const float* bv = (const float*)d_in[6];
    const float* Wo = (const float*)d_in[7];
    const float* bo = (const float*)d_in[8];
    float* out = (float*)d_out;

    __nv_bfloat16 *xhi, *xlo, *w0h, *w0l, *w1h, *w1l, *w2h, *w2l, *w3h, *w3l, *ahi, *alo;
    __nv_bfloat16 *qh, *ql, *kh, *kl, *vh, *vl;
    cudaGetSymbolAddress((void**)&xhi, g_xhi);  cudaGetSymbolAddress((void**)&xlo, g_xlo);
    cudaGetSymbolAddress((void**)&w0h, g_W0hi); cudaGetSymbolAddress((void**)&w0l, g_W0lo);
    cudaGetSymbolAddress((void**)&w1h, g_W1hi); cudaGetSymbolAddress((void**)&w1l, g_W1lo);
    cudaGetSymbolAddress((void**)&w2h, g_W2hi); cudaGetSymbolAddress((void**)&w2l, g_W2lo);
    cudaGetSymbolAddress((void**)&w3h, g_W3hi); cudaGetSymbolAddress((void**)&w3l, g_W3lo);
    cudaGetSymbolAddress((void**)&ahi, g_Ahi);  cudaGetSymbolAddress((void**)&alo, g_Alo);
    cudaGetSymbolAddress((void**)&qh, g_Qhi);   cudaGetSymbolAddress((void**)&ql, g_Qlo);
    cudaGetSymbolAddress((void**)&kh, g_Khi);   cudaGetSymbolAddress((void**)&kl, g_Klo);
    cudaGetSymbolAddress((void**)&vh, g_Vhi);   cudaGetSymbolAddress((void**)&vl, g_Vlo);

    cudaFuncSetAttribute(gemm_qkv, cudaFuncAttributeMaxDynamicSharedMemorySize, GEMM_DSMEM);
    cudaFuncSetAttribute(gemm_out, cudaFuncAttributeMaxDynamicSharedMemorySize, GEMM_DSMEM);
    cudaFuncSetAttribute(flash_mma, cudaFuncAttributeMaxDynamicSharedMemorySize, FLASH_DSMEM);

    split_bf16<<<MTOT * DMODEL / 4 / 256, 256>>>(x, xhi, xlo, MTOT * DMODEL / 4);
    dim3 wgrid(DMODEL * DMODEL / 4 / 256, 4);
    split_bf16_w<<<wgrid, 256>>>(Wq, Wk, Wv, Wo,
                                 w0h, w0l, w1h, w1l, w2h, w2l, w3h, w3l,
                                 DMODEL * DMODEL / 4);

    dim3 qgrid(DMODEL / TN, MTOT / TM, 3);   // (8, 32, 3)
    gemm_qkv<<<qgrid, 256, GEMM_DSMEM>>>(xhi, xlo, w0h, w0l, w1h, w1l, w2h, w2l,
                                         bq, bk, bv, qh, ql, kh, kl, vh, vl);

    dim3 agrid(NSEQ / FBR, BH);              // (16, 32)
    flash_mma<<<agrid, 256, FLASH_DSMEM>>>(qh, ql, kh, kl, vh, vl, ahi, alo);

    dim3 ogrid(DMODEL / TN, MTOT / TM);      // (8, 32)
    gemm_out<<<ogrid, 256, GEMM_DSMEM>>>(ahi, alo, w3h, w3l, bo, out);
}

// round 7
// speedup vs baseline: 3.3432x; 1.0277x over previous
#include <cuda_runtime.h>
#include <cuda_bf16.h>
#include <cstddef>
#include <cstdint>

// Problem constants
#define B_SZ   2
#define NSEQ   2048
#define DMODEL 1024
#define NHEAD  16
#define HDIM   64
#define MTOT   (B_SZ * NSEQ)      // 4096
#define BH     (B_SZ * NHEAD)     // 32

// ---------------------------------------------------------------------------
// Scratch (static device arrays; no allocation allowed)
// ---------------------------------------------------------------------------
__device__ __nv_bfloat16 g_xhi[MTOT * DMODEL];
__device__ __nv_bfloat16 g_xlo[MTOT * DMODEL];
__device__ __nv_bfloat16 g_W0hi[DMODEL * DMODEL];
__device__ __nv_bfloat16 g_W0lo[DMODEL * DMODEL];
__device__ __nv_bfloat16 g_W1hi[DMODEL * DMODEL];
__device__ __nv_bfloat16 g_W1lo[DMODEL * DMODEL];
__device__ __nv_bfloat16 g_W2hi[DMODEL * DMODEL];
__device__ __nv_bfloat16 g_W2lo[DMODEL * DMODEL];
__device__ __nv_bfloat16 g_W3hi[DMODEL * DMODEL];
__device__ __nv_bfloat16 g_W3lo[DMODEL * DMODEL];
__device__ __nv_bfloat16 g_Ahi[MTOT * DMODEL];
__device__ __nv_bfloat16 g_Alo[MTOT * DMODEL];
__device__ __nv_bfloat16 g_Qhi[BH * NSEQ * HDIM];
__device__ __nv_bfloat16 g_Qlo[BH * NSEQ * HDIM];
__device__ __nv_bfloat16 g_Khi[BH * NSEQ * HDIM];
__device__ __nv_bfloat16 g_Klo[BH * NSEQ * HDIM];
__device__ __nv_bfloat16 g_Vhi[BH * NSEQ * HDIM];
__device__ __nv_bfloat16 g_Vlo[BH * NSEQ * HDIM];

// ---------------------------------------------------------------------------
// PTX helpers
// ---------------------------------------------------------------------------
__device__ __forceinline__ uint32_t s2u(const void* p) {
    uint32_t r;
    asm("{ .reg .u64 t; cvta.to.shared.u64 t, %1; cvt.u32.u64 %0, t; }" : "=r"(r) : "l"(p));
    return r;
}
__device__ __forceinline__ void cpa16(uint32_t dst, const void* src) {
    asm volatile("cp.async.cg.shared.global [%0], [%1], 16;" :: "r"(dst), "l"(src));
}
__device__ __forceinline__ void ldsm_x4(uint32_t* r, uint32_t addr) {
    asm volatile("ldmatrix.sync.aligned.m8n8.x4.shared.b16 {%0,%1,%2,%3}, [%4];"
                 : "=r"(r[0]), "=r"(r[1]), "=r"(r[2]), "=r"(r[3]) : "r"(addr));
}
__device__ __forceinline__ void ldsm_x4_t(uint32_t* r, uint32_t addr) {
    asm volatile("ldmatrix.sync.aligned.m8n8.x4.trans.shared.b16 {%0,%1,%2,%3}, [%4];"
                 : "=r"(r[0]), "=r"(r[1]), "=r"(r[2]), "=r"(r[3]) : "r"(addr));
}
__device__ __forceinline__ void mma16816(float* c, const uint32_t* a, const uint32_t* b) {
    asm volatile("mma.sync.aligned.m16n8k16.row.col.f32.bf16.bf16.f32 "
                 "{%0,%1,%2,%3}, {%4,%5,%6,%7}, {%8,%9}, {%0,%1,%2,%3};"
                 : "+f"(c[0]), "+f"(c[1]), "+f"(c[2]), "+f"(c[3])
                 : "r"(a[0]), "r"(a[1]), "r"(a[2]), "r"(a[3]), "r"(b[0]), "r"(b[1]));
}
// Single-instruction exp2 (MUFU.EX2) — exp2f() without fast-math takes the
// slow accurate path; this is the whole point of the base-2 softmax domain.
__device__ __forceinline__ float ex2(float x) {
    float y;
    asm("ex2.approx.f32 %0, %1;" : "=f"(y) : "f"(x));
    return y;
}
__device__ __forceinline__ uint32_t pack2_split(float x, float y, uint32_t& lopack) {
    __nv_bfloat16 hx = __float2bfloat16(x);
    __nv_bfloat16 hy = __float2bfloat16(y);
    __nv_bfloat16 lx = __float2bfloat16(x - __bfloat162float(hx));
    __nv_bfloat16 ly = __float2bfloat16(y - __bfloat162float(hy));
    lopack = (uint32_t)__bfloat16_as_ushort(lx) | ((uint32_t)__bfloat16_as_ushort(ly) << 16);
    return (uint32_t)__bfloat16_as_ushort(hx) | ((uint32_t)__bfloat16_as_ushort(hy) << 16);
}

// ---------------------------------------------------------------------------
// fp32 -> bf16 hi/lo splits
// ---------------------------------------------------------------------------
__global__ void split_bf16(const float* __restrict__ in,
                           __nv_bfloat16* __restrict__ hi,
                           __nv_bfloat16* __restrict__ lo, int n4)
{
    int i = blockIdx.x * blockDim.x + threadIdx.x;
    if (i >= n4) return;
    float4 v = reinterpret_cast<const float4*>(in)[i];
    uint2 h, l;
    h.x = pack2_split(v.x, v.y, l.x);
    h.y = pack2_split(v.z, v.w, l.y);
    reinterpret_cast<uint2*>(hi)[i] = h;
    reinterpret_cast<uint2*>(lo)[i] = l;
}

__global__ void split_bf16_w(const float* __restrict__ w0, const float* __restrict__ w1,
                             const float* __restrict__ w2, const float* __restrict__ w3,
                             __nv_bfloat16* __restrict__ h0, __nv_bfloat16* __restrict__ l0,
                             __nv_bfloat16* __restrict__ h1, __nv_bfloat16* __restrict__ l1,
                             __nv_bfloat16* __restrict__ h2, __nv_bfloat16* __restrict__ l2,
                             __nv_bfloat16* __restrict__ h3, __nv_bfloat16* __restrict__ l3,
                             int n4)
{
    int i = blockIdx.x * blockDim.x + threadIdx.x;
    if (i >= n4) return;
    const float* in; __nv_bfloat16 *hi, *lo;
    switch (blockIdx.y) {
        case 0: in = w0; hi = h0; lo = l0; break;
        case 1: in = w1; hi = h1; lo = l1; break;
        case 2: in = w2; hi = h2; lo = l2; break;
        default: in = w3; hi = h3; lo = l3; break;
    }
    float4 v = reinterpret_cast<const float4*>(in)[i];
    uint2 h, l;
    h.x = pack2_split(v.x, v.y, l.x);
    h.y = pack2_split(v.z, v.w, l.y);
    reinterpret_cast<uint2*>(hi)[i] = h;
    reinterpret_cast<uint2*>(lo)[i] = l;
}

// ---------------------------------------------------------------------------
// HMMA bf16-split GEMM core: 3-stage cp.async pipeline, sync-then-prefetch.
// ---------------------------------------------------------------------------
#define TM 128
#define TN 128
#define KC 32
#define CHUNKS (DMODEL / KC)       // 32
#define TILE_B  8192
#define STAGE_B (4 * TILE_B)       // 32 KB
#define GSTAGES 3
#define GEMM_DSMEM (GSTAGES * STAGE_B)   // 96 KB

__device__ __forceinline__ uint32_t swz(uint32_t row, uint32_t chunk) {
    return row * 64u + ((chunk ^ ((row >> 1) & 3u)) << 4);
}

template <int MODE>
__device__ __forceinline__ void gemm_core(
        const __nv_bfloat16* __restrict__ Ahi, const __nv_bfloat16* __restrict__ Alo,
        const __nv_bfloat16* __restrict__ Bhi, const __nv_bfloat16* __restrict__ Blo,
        const float* __restrict__ bias, float* __restrict__ C,
        __nv_bfloat16* __restrict__ Chi, __nv_bfloat16* __restrict__ Clo,
        float scale, char* dsm, int m0, int n0)
{
    const uint32_t sbase = s2u(dsm);
    const int tid  = threadIdx.x;
    const int wid  = tid >> 5;
    const int lane = tid & 31;
    const int wm = (wid & 3) * 32;
    const int wn = (wid >> 2) * 64;

    float acc[2][8][4];
#pragma unroll
    for (int i = 0; i < 2; i++)
#pragma unroll
        for (int j = 0; j < 8; j++)
#pragma unroll
            for (int q = 0; q < 4; q++) acc[i][j][q] = 0.f;

    const uint32_t lrow = (uint32_t)(tid >> 1);
    const uint32_t lch  = (uint32_t)(tid & 1) * 2;

    auto load_chunk = [&](int ch, int s) {
        const uint32_t sb = sbase + (uint32_t)s * STAGE_B;
        const size_t gA = (size_t)(m0 + lrow) * DMODEL + (size_t)ch * KC + lch * 8;
        const size_t gB = (size_t)(n0 + lrow) * DMODEL + (size_t)ch * KC + lch * 8;
#pragma unroll
        for (int c = 0; c < 2; c++) {
            uint32_t so = swz(lrow, lch + c);
            cpa16(sb + 0 * TILE_B + so, Ahi + gA + c * 8);
            cpa16(sb + 1 * TILE_B + so, Alo + gA + c * 8);
            cpa16(sb + 2 * TILE_B + so, Bhi + gB + c * 8);
            cpa16(sb + 3 * TILE_B + so, Blo + gB + c * 8);
        }
        asm volatile("cp.async.commit_group;" ::: "memory");
    };

    load_chunk(0, 0);
    load_chunk(1, 1);

    int stage = 0;
    for (int ch = 0; ch < CHUNKS; ++ch) {
        if (ch + 1 < CHUNKS) { asm volatile("cp.async.wait_group 1;" ::: "memory"); }
        else                 { asm volatile("cp.async.wait_group 0;" ::: "memory"); }
        __syncthreads();
        if (ch + 2 < CHUNKS) {
            int ps = stage + 2; if (ps >= GSTAGES) ps -= GSTAGES;
            load_chunk(ch + 2, ps);
        }

        const uint32_t sb = sbase + (uint32_t)stage * STAGE_B;
#pragma unroll
        for (int kstep = 0; kstep < 2; kstep++) {
            const uint32_t kc = (uint32_t)kstep * 2;
            uint32_t a_hi[2][4], a_lo[2][4];
#pragma unroll
            for (int mf = 0; mf < 2; mf++) {
                uint32_t row = (uint32_t)(wm + mf * 16 + (lane & 15));
                uint32_t chn = kc + (uint32_t)(lane >> 4);
                ldsm_x4(a_hi[mf], sb + 0 * TILE_B + swz(row, chn));
                ldsm_x4(a_lo[mf], sb + 1 * TILE_B + swz(row, chn));
            }
#pragma unroll
            for (int nf2 = 0; nf2 < 4; nf2++) {
                uint32_t row = (uint32_t)(wn + nf2 * 16 + 8 * (lane >> 4) + (lane & 7));
                uint32_t chn = kc + (uint32_t)((lane >> 3) & 1);
                uint32_t th[4], tl[4];
                ldsm_x4(th, sb + 2 * TILE_B + swz(row, chn));
                ldsm_x4(tl, sb + 3 * TILE_B + swz(row, chn));
#pragma unroll
                for (int mf = 0; mf < 2; mf++) {
                    mma16816(acc[mf][2 * nf2],     a_hi[mf], th);
                    mma16816(acc[mf][2 * nf2 + 1], a_hi[mf], th + 2);
                    mma16816(acc[mf][2 * nf2],     a_hi[mf], tl);
                    mma16816(acc[mf][2 * nf2 + 1], a_hi[mf], tl + 2);
                    mma16816(acc[mf][2 * nf2],     a_lo[mf], th);
                    mma16816(acc[mf][2 * nf2 + 1], a_lo[mf], th + 2);
                }
            }
        }
        if (++stage >= GSTAGES) stage = 0;
    }
    __syncthreads();

#pragma unroll
    for (int mf = 0; mf < 2; mf++) {
        const int rbase = m0 + wm + mf * 16 + (lane >> 2);
#pragma unroll
        for (int nf = 0; nf < 8; nf++) {
            const int n = n0 + wn + nf * 8 + (lane & 3) * 2;
            const float b0 = bias[n], b1 = bias[n + 1];
#pragma unroll
            for (int half = 0; half < 2; half++) {
                const int m = rbase + half * 8;
                float v0 = (acc[mf][nf][2 * half] + b0) * scale;
                float v1 = (acc[mf][nf][2 * half + 1] + b1) * scale;
                if (MODE == 0) {
                    *reinterpret_cast<float2*>(C + (size_t)m * DMODEL + n) =
                        make_float2(v0, v1);
                } else {
                    int h = n >> 6, hd = n & 63;
                    int b  = m >> 11, ns = m & 2047;
                    size_t idx = (((size_t)(b * NHEAD + h) * NSEQ) + ns) * HDIM + hd;
                    uint32_t lp, hp = pack2_split(v0, v1, lp);
                    *reinterpret_cast<uint32_t*>(Chi + idx) = hp;
                    *reinterpret_cast<uint32_t*>(Clo + idx) = lp;
                }
            }
        }
    }
}

// Q pre-scale folds 1/sqrt(HDIM) AND log2(e) so flash uses ex2 directly
#define QSCALE 0.18033688011112042f

__global__ void __launch_bounds__(256, 2)
gemm_qkv(const __nv_bfloat16* __restrict__ xhi, const __nv_bfloat16* __restrict__ xlo,
         const __nv_bfloat16* __restrict__ w0h, const __nv_bfloat16* __restrict__ w0l,
         const __nv_bfloat16* __restrict__ w1h, const __nv_bfloat16* __restrict__ w1l,
         const __nv_bfloat16* __restrict__ w2h, const __nv_bfloat16* __restrict__ w2l,
         const float* __restrict__ bq, const float* __restrict__ bk,
         const float* __restrict__ bv,
         __nv_bfloat16* __restrict__ qh, __nv_bfloat16* __restrict__ ql,
         __nv_bfloat16* __restrict__ kh, __nv_bfloat16* __restrict__ kl,
         __nv_bfloat16* __restrict__ vh, __nv_bfloat16* __restrict__ vl)
{
    extern __shared__ char dsm[];
    const int m0 = blockIdx.y * TM;
    const int n0 = blockIdx.x * TN;
    const __nv_bfloat16 *Bh, *Bl; const float* bias;
    __nv_bfloat16 *Ch, *Cl; float scale;
    switch (blockIdx.z) {
        case 0:  Bh = w0h; Bl = w0l; bias = bq; Ch = qh; Cl = ql; scale = QSCALE; break;
        case 1:  Bh = w1h; Bl = w1l; bias = bk; Ch = kh; Cl = kl; scale = 1.0f;   break;
        default: Bh = w2h; Bl = w2l; bias = bv; Ch = vh; Cl = vl; scale = 1.0f;   break;
    }
    gemm_core<1>(xhi, xlo, Bh, Bl, bias, nullptr, Ch, Cl, scale, dsm, m0, n0);
}

__global__ void __launch_bounds__(256, 2)
gemm_out(const __nv_bfloat16* __restrict__ Ahi, const __nv_bfloat16* __restrict__ Alo,
         const __nv_bfloat16* __restrict__ Bhi, const __nv_bfloat16* __restrict__ Blo,
         const float* __restrict__ bias, float* __restrict__ C)
{
    extern __shared__ char dsm[];
    gemm_core<0>(Ahi, Alo, Bhi, Blo, bias, C, nullptr, nullptr, 1.0f, dsm,
                 blockIdx.y * TM, blockIdx.x * TN);
}

// ---------------------------------------------------------------------------
// HMMA flash attention, bf16-split, 2-stage KV pipeline, 2 CTAs/SM.
// ---------------------------------------------------------------------------
#define FBR 128
#define FBC 64
#define FKT (NSEQ / FBC)          // 32
#define FQHI 0
#define FQLO 16384
#define FSTG0 32768
#define FSTG_B 32768
#define FLASH_DSMEM (32768 + 2 * FSTG_B)   // 96 KB

__device__ __forceinline__ uint32_t swz8(uint32_t row, uint32_t chunk) {
    return row * 128u + ((chunk ^ (row & 7u)) << 4);
}

__global__ void __launch_bounds__(256, 2)
flash_mma(const __nv_bfloat16* __restrict__ Qhi, const __nv_bfloat16* __restrict__ Qlo,
          const __nv_bfloat16* __restrict__ Khi, const __nv_bfloat16* __restrict__ Klo,
          const __nv_bfloat16* __restrict__ Vhi, const __nv_bfloat16* __restrict__ Vlo,
          __nv_bfloat16* __restrict__ Ohi, __nv_bfloat16* __restrict__ Olo)
{
    extern __shared__ char fsm[];
    const uint32_t sbase = s2u(fsm);

    const int tid  = threadIdx.x;
    const int wid  = tid >> 5;
    const int lane = tid & 31;
    const int bh   = blockIdx.y;
    const int q0   = blockIdx.x * FBR;

    const size_t hb = (size_t)bh * NSEQ * HDIM;
    const __nv_bfloat16* Qh = Qhi + hb; const __nv_bfloat16* Ql = Qlo + hb;
    const __nv_bfloat16* Kh = Khi + hb; const __nv_bfloat16* Kl = Klo + hb;
    const __nv_bfloat16* Vh = Vhi + hb; const __nv_bfloat16* Vl = Vlo + hb;

    // Q tile load (joins first KV commit group)
    {
        const uint32_t row = (uint32_t)(tid >> 1);
        const uint32_t c0  = (uint32_t)(tid & 1) * 4;
        const size_t g = (size_t)(q0 + row) * HDIM + c0 * 8;
#pragma unroll
        for (int c = 0; c < 4; c++) {
            uint32_t sw = swz8(row, c0 + c);
            cpa16(sbase + FQHI + sw, Qh + g + c * 8);
            cpa16(sbase + FQLO + sw, Ql + g + c * 8);
        }
    }
    auto load_kv = [&](int kt, int s) {
        const uint32_t sb = sbase + FSTG0 + (uint32_t)s * FSTG_B;
        const uint32_t row = (uint32_t)(tid >> 2);
        const uint32_t cc  = (uint32_t)(tid & 3) * 2;
        const size_t g = (size_t)(kt * FBC + row) * HDIM + cc * 8;
#pragma unroll
        for (int j = 0; j < 2; j++) {
            uint32_t sw = swz8(row, cc + j);
            cpa16(sb +     0u + sw, Kh + g + j * 8);
            cpa16(sb +  8192u + sw, Kl + g + j * 8);
            cpa16(sb + 16384u + sw, Vh + g + j * 8);
            cpa16(sb + 24576u + sw, Vl + g + j * 8);
        }
        asm volatile("cp.async.commit_group;" ::: "memory");
    };
    load_kv(0, 0);

    float o[8][4];
#pragma unroll
    for (int j = 0; j < 8; j++)
#pragma unroll
        for (int q = 0; q < 4; q++) o[j][q] = 0.f;
    float m0s = -1e30f, m1s = -1e30f, l0s = 0.f, l1s = 0.f;

    const uint32_t la15 = (uint32_t)(lane & 15);
    const uint32_t la7  = (uint32_t)(lane & 7);
    const uint32_t lb8  = 8u * (uint32_t)(lane >> 4);
    const uint32_t lbc  = (uint32_t)((lane >> 3) & 1);
    const uint32_t lac  = (uint32_t)(lane >> 4);

    for (int kt = 0; kt < FKT; kt++) {
        asm volatile("cp.async.wait_group 0;" ::: "memory");
        __syncthreads();
        if (kt + 1 < FKT) load_kv(kt + 1, (kt + 1) & 1);

        const uint32_t sb = sbase + FSTG0 + (uint32_t)(kt & 1) * FSTG_B;
        float acc[8][4];
#pragma unroll
        for (int j = 0; j < 8; j++)
#pragma unroll
            for (int q = 0; q < 4; q++) acc[j][q] = 0.f;

        // ---- S = Q K^T
#pragma unroll
        for (int kf = 0; kf < 4; kf++) {
            uint32_t aQh[4], aQl[4];
            uint32_t qad = swz8((uint32_t)(wid * 16) + la15, 2u * kf + lac);
            ldsm_x4(aQh, sbase + FQHI + qad);
            ldsm_x4(aQl, sbase + FQLO + qad);
#pragma unroll
            for (int np = 0; np < 4; np++) {
                uint32_t ad = swz8((uint32_t)(np * 16) + la7 + lb8, 2u * kf + lbc);
                uint32_t kh[4], kl[4];
                ldsm_x4(kh, sb + 0u + ad);
                ldsm_x4(kl, sb + 8192u + ad);
                mma16816(acc[2 * np],     aQh, kh);
                mma16816(acc[2 * np + 1], aQh, kh + 2);
                mma16816(acc[2 * np],     aQh, kl);
                mma16816(acc[2 * np + 1], aQh, kl + 2);
                mma16816(acc[2 * np],     aQl, kh);
                mma16816(acc[2 * np + 1], aQl, kh + 2);
            }
        }

        // ---- online softmax (base-2; single-MUFU ex2)
        float mx0 = -1e30f, mx1 = -1e30f;
#pragma unroll
        for (int nf = 0; nf < 8; nf++) {
            mx0 = fmaxf(mx0, fmaxf(acc[nf][0], acc[nf][1]));
            mx1 = fmaxf(mx1, fmaxf(acc[nf][2], acc[nf][3]));
        }
        mx0 = fmaxf(mx0, __shfl_xor_sync(0xffffffffu, mx0, 1));
        mx0 = fmaxf(mx0, __shfl_xor_sync(0xffffffffu, mx0, 2));
        mx1 = fmaxf(mx1, __shfl_xor_sync(0xffffffffu, mx1, 1));
        mx1 = fmaxf(mx1, __shfl_xor_sync(0xffffffffu, mx1, 2));
        float mn0 = fmaxf(m0s, mx0), mn1 = fmaxf(m1s, mx1);
        float al0 = ex2(m0s - mn0), al1 = ex2(m1s - mn1);
        m0s = mn0; m1s = mn1;
        float sum0 = 0.f, sum1 = 0.f;
#pragma unroll
        for (int nf = 0; nf < 8; nf++) {
            acc[nf][0] = ex2(acc[nf][0] - mn0);
            acc[nf][1] = ex2(acc[nf][1] - mn0);
            acc[nf][2] = ex2(acc[nf][2] - mn1);
            acc[nf][3] = ex2(acc[nf][3] - mn1);
            sum0 += acc[nf][0] + acc[nf][1];
            sum1 += acc[nf][2] + acc[nf][3];
        }
        sum0 += __shfl_xor_sync(0xffffffffu, sum0, 1);
        sum0 += __shfl_xor_sync(0xffffffffu, sum0, 2);
        sum1 += __shfl_xor_sync(0xffffffffu, sum1, 1);
        sum1 += __shfl_xor_sync(0xffffffffu, sum1, 2);
        l0s = l0s * al0 + sum0;
        l1s = l1s * al1 + sum1;
#pragma unroll
        for (int nf = 0; nf < 8; nf++) {
            o[nf][0] *= al0; o[nf][1] *= al0;
            o[nf][2] *= al1; o[nf][3] *= al1;
        }

        // ---- O += P V
#pragma unroll
        for (int kf = 0; kf < 4; kf++) {
            uint32_t pH[4], pL[4];
            pH[0] = pack2_split(acc[2 * kf][0],     acc[2 * kf][1],     pL[0]);
            pH[1] = pack2_split(acc[2 * kf][2],     acc[2 * kf][3],     pL[1]);
            pH[2] = pack2_split(acc[2 * kf + 1][0], acc[2 * kf + 1][1], pL[2]);
            pH[3] = pack2_split(acc[2 * kf + 1][2], acc[2 * kf + 1][3], pL[3]);
#pragma unroll
            for (int dp = 0; dp < 4; dp++) {
                uint32_t ad = swz8((uint32_t)(kf * 16) + la15, 2u * dp + lac);
                uint32_t vh[4], vl[4];
                ldsm_x4_t(vh, sb + 16384u + ad);
                ldsm_x4_t(vl, sb + 24576u + ad);
                mma16816(o[2 * dp],     pH, vh);
                mma16816(o[2 * dp + 1], pH, vh + 2);
                mma16816(o[2 * dp],     pH, vl);
                mma16816(o[2 * dp + 1], pH, vl + 2);
                mma16816(o[2 * dp],     pL, vh);
                mma16816(o[2 * dp + 1], pL, vh + 2);
            }
        }
    }

    // ---- normalize + write bf16 hi/lo to [B,N,D]
    const int bb = bh >> 4;
    const int h  = bh & 15;
    const float inv0 = 1.f / l0s, inv1 = 1.f / l1s;
    const int qlo = q0 + wid * 16 + (lane >> 2);
#pragma unroll
    for (int nf = 0; nf < 8; nf++) {
        const int gcol = h * HDIM + nf * 8 + (lane & 3) * 2;
        uint32_t lp, hp;
        hp = pack2_split(o[nf][0] * inv0, o[nf][1] * inv0, lp);
        size_t i0 = ((size_t)(bb * NSEQ + qlo)) * DMODEL + gcol;
        *reinterpret_cast<uint32_t*>(Ohi + i0) = hp;
        *reinterpret_cast<uint32_t*>(Olo + i0) = lp;
        hp = pack2_split(o[nf][2] * inv1, o[nf][3] * inv1, lp);
        size_t i1 = ((size_t)(bb * NSEQ + qlo + 8)) * DMODEL + gcol;
        *reinterpret_cast<uint32_t*>(Ohi + i1) = hp;
        *reinterpret_cast<uint32_t*>(Olo + i1) = lp;
    }
}

// ---------------------------------------------------------------------------
// Launch
// ---------------------------------------------------------------------------
extern "C" void kernel_launch(void* const* d_in, const int* in_sizes, int n_in,
                              void* d_out, int out_size)
{
    const float* x  = (const float*)d_in[0];
    const float* Wq = (const float*)d_in[1];
    const float* bq = (const float*)d_in[2];
    const float* Wk = (const float*)d_in[3];
    const float* bk = (const float*)d_in[4];
    const float* Wv = (const float*)d_in[5];
    const float* bv = (const float*)d_in[6];
    const float* Wo = (const float*)d_in[7];
    const float* bo = (const float*)d_in[8];
    float* out = (float*)d_out;

    __nv_bfloat16 *xhi, *xlo, *w0h, *w0l, *w1h, *w1l, *w2h, *w2l, *w3h, *w3l, *ahi, *alo;
    __nv_bfloat16 *qh, *ql, *kh, *kl, *vh, *vl;
    cudaGetSymbolAddress((void**)&xhi, g_xhi);  cudaGetSymbolAddress((void**)&xlo, g_xlo);
    cudaGetSymbolAddress((void**)&w0h, g_W0hi); cudaGetSymbolAddress((void**)&w0l, g_W0lo);
    cudaGetSymbolAddress((void**)&w1h, g_W1hi); cudaGetSymbolAddress((void**)&w1l, g_W1lo);
    cudaGetSymbolAddress((void**)&w2h, g_W2hi); cudaGetSymbolAddress((void**)&w2l, g_W2lo);
    cudaGetSymbolAddress((void**)&w3h, g_W3hi); cudaGetSymbolAddress((void**)&w3l, g_W3lo);
    cudaGetSymbolAddress((void**)&ahi, g_Ahi);  cudaGetSymbolAddress((void**)&alo, g_Alo);
    cudaGetSymbolAddress((void**)&qh, g_Qhi);   cudaGetSymbolAddress((void**)&ql, g_Qlo);
    cudaGetSymbolAddress((void**)&kh, g_Khi);   cudaGetSymbolAddress((void**)&kl, g_Klo);
    cudaGetSymbolAddress((void**)&vh, g_Vhi);   cudaGetSymbolAddress((void**)&vl, g_Vlo);

    cudaFuncSetAttribute(gemm_qkv, cudaFuncAttributeMaxDynamicSharedMemorySize, GEMM_DSMEM);
    cudaFuncSetAttribute(gemm_out, cudaFuncAttributeMaxDynamicSharedMemorySize, GEMM_DSMEM);
    cudaFuncSetAttribute(flash_mma, cudaFuncAttributeMaxDynamicSharedMemorySize, FLASH_DSMEM);

    split_bf16<<<MTOT * DMODEL / 4 / 256, 256>>>(x, xhi, xlo, MTOT * DMODEL / 4);
    dim3 wgrid(DMODEL * DMODEL / 4 / 256, 4);
    split_bf16_w<<<wgrid, 256>>>(Wq, Wk, Wv, Wo,
                                 w0h, w0l, w1h, w1l, w2h, w2l, w3h, w3l,
                                 DMODEL * DMODEL / 4);

    dim3 qgrid(DMODEL / TN, MTOT / TM, 3);   // (8, 32, 3)
    gemm_qkv<<<qgrid, 256, GEMM_DSMEM>>>(xhi, xlo, w0h, w0l, w1h, w1l, w2h, w2l,
                                         bq, bk, bv, qh, ql, kh, kl, vh, vl);

    dim3 agrid(NSEQ / FBR, BH);              // (16, 32)
    flash_mma<<<agrid, 256, FLASH_DSMEM>>>(qh, ql, kh, kl, vh, vl, ahi, alo);

    dim3 ogrid(DMODEL / TN, MTOT / TM);      // (8, 32)
    gemm_out<<<ogrid, 256, GEMM_DSMEM>>>(ahi, alo, w3h, w3l, bo, out);
}